// round 10
// baseline (speedup 1.0000x reference)
#include <cuda_runtime.h>
#include <cuda_fp16.h>
#include <cstdint>

#define N_NODES 50000
#define EMBED 128
#define HIDDEN 256
#define N_EDGES 640000
#define LN_EPS 1e-5f

typedef unsigned long long u64t;

// ---------------- FFMA2 helpers ----------------
#define FMA2(d, a, b, c) \
    asm("fma.rn.f32x2 %0, %1, %2, %3;" : "=l"(d) : "l"(a), "l"(b), "l"(c))
#define DUP2(d, x) \
    asm("mov.b64 %0, {%1, %1};" : "=l"(d) : "f"(x))
#define UNPK2(lo, hi, p) \
    asm("mov.b64 {%0, %1}, %2;" : "=f"(lo), "=f"(hi) : "l"(p))

// ---------------- warp MMA / cp.async helpers (sm_80-class) ----------------
__device__ __forceinline__ uint32_t smem_u32(const void* p) {
    uint32_t a;
    asm("{ .reg .u64 t; cvta.to.shared.u64 t, %1; cvt.u32.u64 %0, t; }"
        : "=r"(a) : "l"(p));
    return a;
}
__device__ __forceinline__ void mma_f16(float* d, const uint32_t* a, const uint32_t* b) {
    asm volatile(
        "mma.sync.aligned.m16n8k16.row.col.f32.f16.f16.f32 "
        "{%0,%1,%2,%3}, {%4,%5,%6,%7}, {%8,%9}, {%0,%1,%2,%3};"
        : "+f"(d[0]), "+f"(d[1]), "+f"(d[2]), "+f"(d[3])
        : "r"(a[0]), "r"(a[1]), "r"(a[2]), "r"(a[3]), "r"(b[0]), "r"(b[1]));
}
__device__ __forceinline__ void ldm4(uint32_t* r, uint32_t addr) {
    asm volatile("ldmatrix.sync.aligned.m8n8.x4.shared.b16 {%0,%1,%2,%3}, [%4];"
                 : "=r"(r[0]), "=r"(r[1]), "=r"(r[2]), "=r"(r[3]) : "r"(addr));
}
__device__ __forceinline__ void ldm2(uint32_t* r, uint32_t addr) {
    asm volatile("ldmatrix.sync.aligned.m8n8.x2.shared.b16 {%0,%1}, [%2];"
                 : "=r"(r[0]), "=r"(r[1]) : "r"(addr));
}
__device__ __forceinline__ void cpa16(uint32_t dst, const void* src) {
    asm volatile("cp.async.cg.shared.global [%0], [%1], 16;" :: "r"(dst), "l"(src));
}
#define CP_COMMIT() asm volatile("cp.async.commit_group;" ::: "memory")
#define CP_WAIT(n)  asm volatile("cp.async.wait_group %0;" :: "n"(n) : "memory")

__device__ __forceinline__ float silu_f(float x) {
    return __fdividef(x, 1.0f + __expf(-x));
}

// ---------------- device scratch ----------------
__device__ float g_h[N_NODES * EMBED];     // layernormed node embeddings
__device__ float g_agg[N_NODES * EMBED];   // init to h; edge atomics add msg
__device__ __align__(16) __half g_w1h[32768];   // W1^T [n=256][k=128]
__device__ __align__(16) __half g_w2h[32768];   // W2^T [n=128][kk=256]
__device__ __align__(16) __half g_wth[16384];   // Wt^T [n=128][k=128]

// ---------------------------------------------------------------------------
// Kernel 1 (fused): blocks 0..127 weight prep; rest LayerNorm (warp/row).
// ---------------------------------------------------------------------------
#define PREP_BLOCKS 128

__global__ void init_kernel(const float* __restrict__ x,
                            const float* __restrict__ gamma,
                            const float* __restrict__ beta,
                            const float* __restrict__ W1,
                            const float* __restrict__ W2,
                            const float* __restrict__ Wt) {
    if (blockIdx.x < PREP_BLOCKS) {
        int idx = blockIdx.x * blockDim.x + threadIdx.x;   // 0..32767
        {   int k = idx >> 8, n = idx & 255;
            g_w1h[n * 128 + k] = __float2half_rn(W1[idx]); }
        {   int kk = idx >> 7, n = idx & 127;
            g_w2h[n * 256 + kk] = __float2half_rn(W2[idx]); }
        if (idx < 16384) {
            int k = idx >> 7, n = idx & 127;
            g_wth[n * 128 + k] = __float2half_rn(Wt[idx]);
        }
        return;
    }

    int warp = ((blockIdx.x - PREP_BLOCKS) * blockDim.x + threadIdx.x) >> 5;
    int lane = threadIdx.x & 31;
    if (warp >= N_NODES) return;

    const float4* row = (const float4*)(x + (size_t)warp * EMBED);
    float4 v = row[lane];
    float s  = v.x + v.y + v.z + v.w;
    float ss = v.x * v.x + v.y * v.y + v.z * v.z + v.w * v.w;
    #pragma unroll
    for (int o = 16; o; o >>= 1) {
        s  += __shfl_xor_sync(0xFFFFFFFFu, s,  o);
        ss += __shfl_xor_sync(0xFFFFFFFFu, ss, o);
    }
    const float inv_d = 1.0f / (float)EMBED;
    float mu  = s * inv_d;
    float var = ss * inv_d - mu * mu;
    float inv = rsqrtf(var + LN_EPS);

    float4 g = ((const float4*)gamma)[lane];
    float4 b = ((const float4*)beta)[lane];
    float4 o4;
    o4.x = (v.x - mu) * inv * g.x + b.x;
    o4.y = (v.y - mu) * inv * g.y + b.y;
    o4.z = (v.z - mu) * inv * g.z + b.z;
    o4.w = (v.w - mu) * inv * g.w + b.w;
    ((float4*)(g_h + (size_t)warp * EMBED))[lane] = o4;
    ((float4*)(g_agg + (size_t)warp * EMBED))[lane] = o4;   // agg starts at h
}

// ---------------------------------------------------------------------------
// Kernel 2: hybrid tensor(112 cols) + FMA2(16 cols) edge MLP.
// 128 edges/CTA, 8 warps, 2 CTAs/SM.
// ---------------------------------------------------------------------------
#define TE 128
#define ETH 256
#define A_STRIDE 264   // halves; 528B rows
#define B_STRIDE 136   // halves; 272B rows
#define NT_T 14        // tensor n-tiles per phase (cols 0..111)
#define FC0 112        // fma col base within each 128-col phase

#define SM_CI   0
#define SM_NI   512
#define SM_B1   1024
#define SM_B2   2048
#define SM_A    2560
#define SM_B    (SM_A + 128 * A_STRIDE * 2)     // 70144
#define SM_WF   (SM_B + 112 * B_STRIDE * 2)     // 100608 (fp32 W slice 128k x 16c)
#define EDGE_SMEM (SM_WF + 128 * 16 * 4)        // 108800 -> 2 CTAs/SM

// fp16 B tile: only 112 n-rows needed by tensor path
__device__ __forceinline__ void cp_tile(uint32_t sdst,
                                        const __half* __restrict__ src,
                                        int src_stride_halves, int tid) {
    #pragma unroll
    for (int i = tid; i < 1792; i += ETH) {
        int r = i >> 4, c = i & 15;
        cpa16(sdst + r * (B_STRIDE * 2) + c * 16,
              src + r * src_stride_halves + c * 8);
    }
}
// fp32 W slice: 128 k-rows x 16 cols (64B/row), from row-major W [k][n]
__device__ __forceinline__ void cp_wf(uint32_t sdst,
                                      const float* __restrict__ src,
                                      int row_stride_f, int col0, int tid) {
    #pragma unroll
    for (int i = tid; i < 512; i += ETH) {
        int k = i >> 2, c4 = i & 3;
        cpa16(sdst + k * 64 + c4 * 16, src + k * row_stride_f + col0 + c4 * 4);
    }
}

__global__ __launch_bounds__(ETH, 2)
void edge_kernel(const float* __restrict__ eemb,
                 const int* __restrict__ eidx,
                 const float* __restrict__ b1g,
                 const float* __restrict__ b2g,
                 const float* __restrict__ W1f,
                 const float* __restrict__ W2f) {
    extern __shared__ char smem[];
    uint32_t sbase = smem_u32(smem);
    int tid = threadIdx.x, wid = tid >> 5, lane = tid & 31;
    int e0 = blockIdx.x * TE;

    int*   s_ci = (int*)(smem + SM_CI);
    int*   s_ni = (int*)(smem + SM_NI);
    float* sb1  = (float*)(smem + SM_B1);
    float* sb2  = (float*)(smem + SM_B2);

    // stage 0: W1 n-half0 fp16 tile + fp32 fma slice
    cp_tile(sbase + SM_B, g_w1h, 128, tid);
    cp_wf(sbase + SM_WF, W1f, 256, FC0, tid);
    CP_COMMIT();

    if (tid < 128) {
        s_ci[tid] = eidx[e0 + tid];
        s_ni[tid] = eidx[N_EDGES + e0 + tid];
    }
    sb1[tid] = b1g[tid];
    if (tid < 128) sb2[tid] = b2g[tid];
    __syncthreads();

    // ---- gather: A1 = fp16(silu(e + h_c + h_n)) into A cols 0..127 ----
    #pragma unroll
    for (int it = 0; it < 16; it++) {
        int v = tid + ETH * it;
        int m = v >> 5, c = v & 31;
        float4 ee = ((const float4*)(eemb + (size_t)(e0 + m) * EMBED))[c];
        float4 hc = ((const float4*)(g_h + (size_t)s_ci[m] * EMBED))[c];
        float4 hn = ((const float4*)(g_h + (size_t)s_ni[m] * EMBED))[c];
        float s0 = silu_f(ee.x + hc.x + hn.x);
        float s1 = silu_f(ee.y + hc.y + hn.y);
        float s2 = silu_f(ee.z + hc.z + hn.z);
        float s3 = silu_f(ee.w + hc.w + hn.w);
        int off = (m * A_STRIDE + 4 * c) * 2;
        *(__half2*)(smem + SM_A + off)     = __floats2half2_rn(s0, s1);
        *(__half2*)(smem + SM_A + off + 4) = __floats2half2_rn(s2, s3);
    }

    int rb = wid * 16;
    int ai = lane & 7, as_ = lane >> 3;
    int arow = rb + ai + (as_ & 1) * 8;
    int acolseg = (as_ >> 1) * 8;
    int bi = lane & 7, bs = (lane >> 3) & 1;
    int q = lane & 3;
    int r0 = rb + (lane >> 2), r1 = r0 + 8;
    // fma-path ownership: 1 row x 8 cols per thread (warp-private row block)
    int frow = tid >> 1;
    int fcb  = FC0 + (tid & 1) * 8;          // col base within phase
    uint32_t fwoff = (uint32_t)((tid & 1) * 32);

    // ================= GEMM1 (two n-halves) =================
    #pragma unroll 1
    for (int h = 0; h < 2; h++) {
        CP_WAIT(0);
        __syncthreads();

        float acc[NT_T][4];
        #pragma unroll
        for (int i = 0; i < NT_T; i++)
            #pragma unroll
            for (int j = 0; j < 4; j++) acc[i][j] = 0.f;
        u64t accf[4];
        #pragma unroll
        for (int i = 0; i < 4; i++) accf[i] = 0ull;

        #pragma unroll
        for (int ks = 0; ks < 8; ks++) {
            uint32_t a4[4];
            uint32_t aoff = (uint32_t)(arow * A_STRIDE + ks * 16 + acolseg) * 2;
            ldm4(a4, sbase + SM_A + aoff);
            #pragma unroll
            for (int nt = 0; nt < NT_T; nt++) {
                uint32_t boff = (uint32_t)((nt * 8 + bi) * B_STRIDE + ks * 16 + bs * 8) * 2;
                uint32_t bw[2];
                ldm2(bw, sbase + SM_B + boff);
                mma_f16(acc[nt], a4, bw);
            }
            // fma slice: cols FC0..FC0+15, interleaved with tensor drain
            #pragma unroll
            for (int j = 0; j < 16; j++) {
                int kk = ks * 16 + j;
                float af = __half2float(*(__half*)(smem + SM_A + (frow * A_STRIDE + kk) * 2));
                u64t a2; DUP2(a2, af);
                uint32_t wrow = sbase + SM_WF + (uint32_t)kk * 64 + fwoff;
                u64t w0 = *(u64t*)(smem + (wrow - sbase));
                u64t w1 = *(u64t*)(smem + (wrow - sbase) + 8);
                u64t w2 = *(u64t*)(smem + (wrow - sbase) + 16);
                u64t w3 = *(u64t*)(smem + (wrow - sbase) + 24);
                FMA2(accf[0], a2, w0, accf[0]);
                FMA2(accf[1], a2, w1, accf[1]);
                FMA2(accf[2], a2, w2, accf[2]);
                FMA2(accf[3], a2, w3, accf[3]);
            }
        }
        __syncthreads();

        // stage next: h0 -> W1 half1 ; h1 -> W2 phase0
        if (h == 0) {
            cp_tile(sbase + SM_B, g_w1h + 128 * 128, 128, tid);
            cp_wf(sbase + SM_WF, W1f, 256, 128 + FC0, tid);
        } else {
            cp_tile(sbase + SM_B, g_w2h, 256, tid);
            cp_wf(sbase + SM_WF, W2f, 128, FC0, tid);
        }
        CP_COMMIT();

        // conversion tensor part: t cols 0..111 of this half
        int dbase = (h == 0) ? 128 : 0;
        #pragma unroll
        for (int nt = 0; nt < NT_T; nt++) {
            int c0 = nt * 8 + 2 * q;
            int gc = h * 128 + c0;
            float t0 = silu_f(acc[nt][0] + sb1[gc]);
            float t1 = silu_f(acc[nt][1] + sb1[gc + 1]);
            float t2 = silu_f(acc[nt][2] + sb1[gc]);
            float t3 = silu_f(acc[nt][3] + sb1[gc + 1]);
            int o0 = (r0 * A_STRIDE + dbase + c0) * 2;
            int o1 = (r1 * A_STRIDE + dbase + c0) * 2;
            *(__half2*)(smem + SM_A + o0) = __floats2half2_rn(t0, t1);
            *(__half2*)(smem + SM_A + o1) = __floats2half2_rn(t2, t3);
        }
        // conversion fma part: t cols FC0..FC0+15 of this half
        {
            float f[8];
            UNPK2(f[0], f[1], accf[0]);
            UNPK2(f[2], f[3], accf[1]);
            UNPK2(f[4], f[5], accf[2]);
            UNPK2(f[6], f[7], accf[3]);
            #pragma unroll
            for (int j = 0; j < 4; j++) {
                int gc = h * 128 + fcb + 2 * j;
                float t0 = silu_f(f[2 * j]     + sb1[gc]);
                float t1 = silu_f(f[2 * j + 1] + sb1[gc + 1]);
                int oo = (frow * A_STRIDE + dbase + fcb + 2 * j) * 2;
                *(__half2*)(smem + SM_A + oo) = __floats2half2_rn(t0, t1);
            }
        }
    }

    // ================= GEMM2 (two k-phases) =============
    float acc2[NT_T][4];
    #pragma unroll
    for (int i = 0; i < NT_T; i++)
        #pragma unroll
        for (int j = 0; j < 4; j++) acc2[i][j] = 0.f;
    u64t acc2f[4];
    #pragma unroll
    for (int i = 0; i < 4; i++) acc2f[i] = 0ull;

    #pragma unroll 1
    for (int ph = 0; ph < 2; ph++) {
        CP_WAIT(0);
        __syncthreads();

        int abase = (ph == 0) ? 128 : 0;
        #pragma unroll
        for (int ks = 0; ks < 8; ks++) {
            uint32_t a4[4];
            uint32_t aoff = (uint32_t)(arow * A_STRIDE + abase + ks * 16 + acolseg) * 2;
            ldm4(a4, sbase + SM_A + aoff);
            #pragma unroll
            for (int nt = 0; nt < NT_T; nt++) {
                uint32_t boff = (uint32_t)((nt * 8 + bi) * B_STRIDE + ks * 16 + bs * 8) * 2;
                uint32_t bw[2];
                ldm2(bw, sbase + SM_B + boff);
                mma_f16(acc2[nt], a4, bw);
            }
            #pragma unroll
            for (int j = 0; j < 16; j++) {
                int kk = ks * 16 + j;
                float af = __half2float(
                    *(__half*)(smem + SM_A + (frow * A_STRIDE + abase + kk) * 2));
                u64t a2; DUP2(a2, af);
                uint32_t wofs = SM_WF + (uint32_t)kk * 64 + fwoff;
                u64t w0 = *(u64t*)(smem + wofs);
                u64t w1 = *(u64t*)(smem + wofs + 8);
                u64t w2 = *(u64t*)(smem + wofs + 16);
                u64t w3 = *(u64t*)(smem + wofs + 24);
                FMA2(acc2f[0], a2, w0, acc2f[0]);
                FMA2(acc2f[1], a2, w1, acc2f[1]);
                FMA2(acc2f[2], a2, w2, acc2f[2]);
                FMA2(acc2f[3], a2, w3, acc2f[3]);
            }
        }
        if (ph == 0) {
            __syncthreads();
            cp_tile(sbase + SM_B, g_w2h + 128, 256, tid);
            cp_wf(sbase + SM_WF, W2f + 128 * 128, 128, FC0, tid);
            CP_COMMIT();
        }
    }

    // ---- epilogue tensor part (cols 0..111) ----
    {
        int ci0 = s_ci[r0], ci1 = s_ci[r1];
        int ni0 = s_ni[r0], ni1 = s_ni[r1];
        const float* hn0 = g_h + (size_t)ni0 * EMBED;
        const float* hn1 = g_h + (size_t)ni1 * EMBED;
        float* ag0 = g_agg + (size_t)ci0 * EMBED;
        float* ag1 = g_agg + (size_t)ci1 * EMBED;
        #pragma unroll
        for (int nt = 0; nt < NT_T; nt++) {
            int c0 = nt * 8 + 2 * q;
            float2 h0 = *(const float2*)(hn0 + c0);
            float2 h1 = *(const float2*)(hn1 + c0);
            atomicAdd(ag0 + c0,     (acc2[nt][0] + sb2[c0])     * h0.x);
            atomicAdd(ag0 + c0 + 1, (acc2[nt][1] + sb2[c0 + 1]) * h0.y);
            atomicAdd(ag1 + c0,     (acc2[nt][2] + sb2[c0])     * h1.x);
            atomicAdd(ag1 + c0 + 1, (acc2[nt][3] + sb2[c0 + 1]) * h1.y);
        }
    }
    // ---- epilogue fma part (cols FC0..127, row frow) ----
    {
        float f[8];
        UNPK2(f[0], f[1], acc2f[0]);
        UNPK2(f[2], f[3], acc2f[1]);
        UNPK2(f[4], f[5], acc2f[2]);
        UNPK2(f[6], f[7], acc2f[3]);
        int ctr = s_ci[frow], nbr = s_ni[frow];
        const float* hn = g_h + (size_t)nbr * EMBED;
        float* ag = g_agg + (size_t)ctr * EMBED;
        #pragma unroll
        for (int j = 0; j < 4; j++) {
            int c0 = fcb + 2 * j;
            float2 hv = *(const float2*)(hn + c0);
            atomicAdd(ag + c0,     (f[2 * j]     + sb2[c0])     * hv.x);
            atomicAdd(ag + c0 + 1, (f[2 * j + 1] + sb2[c0 + 1]) * hv.y);
        }
    }
}

// ---------------------------------------------------------------------------
// Kernel 3: out = silu(g_agg) @ Wt + bt   (unchanged from R9)
// ---------------------------------------------------------------------------
#define ONR 64
#define OSM_BT  0
#define OSM_A   512
#define OSM_B   (OSM_A + ONR * B_STRIDE * 2)
#define OUT_SMEM (OSM_B + 128 * B_STRIDE * 2)

__device__ __forceinline__ void cp_tile_full(uint32_t sdst,
                                             const __half* __restrict__ src,
                                             int src_stride_halves, int tid) {
    #pragma unroll
    for (int i = tid; i < 2048; i += 256) {
        int r = i >> 4, c = i & 15;
        cpa16(sdst + r * (B_STRIDE * 2) + c * 16,
              src + r * src_stride_halves + c * 8);
    }
}

__global__ __launch_bounds__(256, 3)
void out_kernel(const float* __restrict__ btg, float* __restrict__ out) {
    extern __shared__ char smem[];
    uint32_t sbase = smem_u32(smem);
    int tid = threadIdx.x, wid = tid >> 5, lane = tid & 31;
    int n0 = blockIdx.x * ONR;

    float* sbt = (float*)(smem + OSM_BT);

    cp_tile_full(sbase + OSM_B, g_wth, 128, tid); CP_COMMIT();
    if (tid < 128) sbt[tid] = btg[tid];

    #pragma unroll
    for (int it = 0; it < 8; it++) {
        int v = tid + 256 * it;
        int m = v >> 5, c = v & 31;
        int row = n0 + m;
        float s0 = 0.f, s1 = 0.f, s2 = 0.f, s3 = 0.f;
        if (row < N_NODES) {
            float4 av = ((const float4*)(g_agg + (size_t)row * EMBED))[c];
            s0 = silu_f(av.x);
            s1 = silu_f(av.y);
            s2 = silu_f(av.z);
            s3 = silu_f(av.w);
        }
        int off = (m * B_STRIDE + 4 * c) * 2;
        *(__half2*)(smem + OSM_A + off)     = __floats2half2_rn(s0, s1);
        *(__half2*)(smem + OSM_A + off + 4) = __floats2half2_rn(s2, s3);
    }

    CP_WAIT(0);
    __syncthreads();

    if (wid < 4) {
        int rb = wid * 16;
        int ai = lane & 7, as_ = lane >> 3;
        int arow = rb + ai + (as_ & 1) * 8;
        int acolseg = (as_ >> 1) * 8;
        int bi = lane & 7, bs = (lane >> 3) & 1;
        int q = lane & 3;
        int r0 = rb + (lane >> 2), r1 = r0 + 8;

        float acc[16][4];
        #pragma unroll
        for (int i = 0; i < 16; i++)
            #pragma unroll
            for (int j = 0; j < 4; j++) acc[i][j] = 0.f;

        #pragma unroll
        for (int ks = 0; ks < 8; ks++) {
            uint32_t a4[4];
            uint32_t aoff = (uint32_t)(arow * B_STRIDE + ks * 16 + acolseg) * 2;
            ldm4(a4, sbase + OSM_A + aoff);
            #pragma unroll
            for (int nt = 0; nt < 16; nt++) {
                uint32_t boff = (uint32_t)((nt * 8 + bi) * B_STRIDE + ks * 16 + bs * 8) * 2;
                uint32_t bw[2];
                ldm2(bw, sbase + OSM_B + boff);
                mma_f16(acc[nt], a4, bw);
            }
        }

        int row0 = n0 + r0, row1 = n0 + r1;
        #pragma unroll
        for (int nt = 0; nt < 16; nt++) {
            int c0 = nt * 8 + 2 * q;
            float2 b2 = *(const float2*)(sbt + c0);
            if (row0 < N_NODES) {
                float2 o0 = make_float2(acc[nt][0] + b2.x, acc[nt][1] + b2.y);
                *(float2*)(out + (size_t)row0 * EMBED + c0) = o0;
            }
            if (row1 < N_NODES) {
                float2 o1 = make_float2(acc[nt][2] + b2.x, acc[nt][3] + b2.y);
                *(float2*)(out + (size_t)row1 * EMBED + c0) = o1;
            }
        }
    }
}

// ---------------------------------------------------------------------------
extern "C" void kernel_launch(void* const* d_in, const int* in_sizes, int n_in,
                              void* d_out, int out_size) {
    const float* node  = (const float*)d_in[0];
    const float* eemb  = (const float*)d_in[1];
    const int*   eidx  = (const int*)  d_in[2];
    const float* gamma = (const float*)d_in[3];
    const float* beta  = (const float*)d_in[4];
    const float* W1    = (const float*)d_in[5];
    const float* b1    = (const float*)d_in[6];
    const float* W2    = (const float*)d_in[7];
    const float* b2    = (const float*)d_in[8];
    const float* Wt    = (const float*)d_in[9];
    const float* bt    = (const float*)d_in[10];
    float* out = (float*)d_out;

    cudaFuncSetAttribute(edge_kernel, cudaFuncAttributeMaxDynamicSharedMemorySize,
                         EDGE_SMEM);
    cudaFuncSetAttribute(out_kernel, cudaFuncAttributeMaxDynamicSharedMemorySize,
                         OUT_SMEM);

    init_kernel<<<PREP_BLOCKS + (N_NODES + 7) / 8, 256>>>(node, gamma, beta, W1, W2, Wt);
    edge_kernel<<<N_EDGES / TE, ETH, EDGE_SMEM>>>(eemb, eidx, b1, b2, W1, W2);
    out_kernel<<<(N_NODES + ONR - 1) / ONR, 256, OUT_SMEM>>>(bt, out);
}

// round 11
// speedup vs baseline: 1.5162x; 1.5162x over previous
#include <cuda_runtime.h>
#include <cuda_fp16.h>
#include <cstdint>

#define N_NODES 50000
#define EMBED 128
#define HIDDEN 256
#define N_EDGES 640000
#define LN_EPS 1e-5f

// ---------------- warp MMA / cp.async helpers (sm_80-class) ----------------
__device__ __forceinline__ uint32_t smem_u32(const void* p) {
    uint32_t a;
    asm("{ .reg .u64 t; cvta.to.shared.u64 t, %1; cvt.u32.u64 %0, t; }"
        : "=r"(a) : "l"(p));
    return a;
}
__device__ __forceinline__ void mma_f16(float* d, const uint32_t* a, const uint32_t* b) {
    asm volatile(
        "mma.sync.aligned.m16n8k16.row.col.f32.f16.f16.f32 "
        "{%0,%1,%2,%3}, {%4,%5,%6,%7}, {%8,%9}, {%0,%1,%2,%3};"
        : "+f"(d[0]), "+f"(d[1]), "+f"(d[2]), "+f"(d[3])
        : "r"(a[0]), "r"(a[1]), "r"(a[2]), "r"(a[3]), "r"(b[0]), "r"(b[1]));
}
__device__ __forceinline__ void ldm4(uint32_t* r, uint32_t addr) {
    asm volatile("ldmatrix.sync.aligned.m8n8.x4.shared.b16 {%0,%1,%2,%3}, [%4];"
                 : "=r"(r[0]), "=r"(r[1]), "=r"(r[2]), "=r"(r[3]) : "r"(addr));
}
__device__ __forceinline__ void ldm2(uint32_t* r, uint32_t addr) {
    asm volatile("ldmatrix.sync.aligned.m8n8.x2.shared.b16 {%0,%1}, [%2];"
                 : "=r"(r[0]), "=r"(r[1]) : "r"(addr));
}
__device__ __forceinline__ void cpa16(uint32_t dst, const void* src) {
    asm volatile("cp.async.cg.shared.global [%0], [%1], 16;" :: "r"(dst), "l"(src));
}
#define CP_COMMIT() asm volatile("cp.async.commit_group;" ::: "memory")
#define CP_WAIT(n)  asm volatile("cp.async.wait_group %0;" :: "n"(n) : "memory")

__device__ __forceinline__ float silu_f(float x) {
    return __fdividef(x, 1.0f + __expf(-x));
}

// ---------------- device scratch ----------------
__device__ float g_h[N_NODES * EMBED];     // layernormed node embeddings
__device__ float g_agg[N_NODES * EMBED];   // init to h; edge atomics add msg -> h+agg
__device__ __align__(16) __half g_w1h[32768];   // W1^T [n=256][k=128]
__device__ __align__(16) __half g_w2h[32768];   // W2^T [n=128][kk=256]
__device__ __align__(16) __half g_wth[16384];   // Wt^T [n=128][k=128]

// ---------------------------------------------------------------------------
// Kernel 1 (fused): blocks 0..127 = weight prep; rest = LayerNorm (warp/row).
// ln writes h into BOTH g_h and g_agg (so edge atomics accumulate onto h).
// ---------------------------------------------------------------------------
#define PREP_BLOCKS 128

__global__ void init_kernel(const float* __restrict__ x,
                            const float* __restrict__ gamma,
                            const float* __restrict__ beta,
                            const float* __restrict__ W1,
                            const float* __restrict__ W2,
                            const float* __restrict__ Wt) {
    if (blockIdx.x < PREP_BLOCKS) {
        int idx = blockIdx.x * blockDim.x + threadIdx.x;   // 0..32767
        {   int k = idx >> 8, n = idx & 255;
            g_w1h[n * 128 + k] = __float2half_rn(W1[idx]); }
        {   int kk = idx >> 7, n = idx & 127;
            g_w2h[n * 256 + kk] = __float2half_rn(W2[idx]); }
        if (idx < 16384) {
            int k = idx >> 7, n = idx & 127;
            g_wth[n * 128 + k] = __float2half_rn(Wt[idx]);
        }
        return;
    }

    int warp = ((blockIdx.x - PREP_BLOCKS) * blockDim.x + threadIdx.x) >> 5;
    int lane = threadIdx.x & 31;
    if (warp >= N_NODES) return;

    const float4* row = (const float4*)(x + (size_t)warp * EMBED);
    float4 v = row[lane];
    float s  = v.x + v.y + v.z + v.w;
    float ss = v.x * v.x + v.y * v.y + v.z * v.z + v.w * v.w;
    #pragma unroll
    for (int o = 16; o; o >>= 1) {
        s  += __shfl_xor_sync(0xFFFFFFFFu, s,  o);
        ss += __shfl_xor_sync(0xFFFFFFFFu, ss, o);
    }
    const float inv_d = 1.0f / (float)EMBED;
    float mu  = s * inv_d;
    float var = ss * inv_d - mu * mu;
    float inv = rsqrtf(var + LN_EPS);

    float4 g = ((const float4*)gamma)[lane];
    float4 b = ((const float4*)beta)[lane];
    float4 o4;
    o4.x = (v.x - mu) * inv * g.x + b.x;
    o4.y = (v.y - mu) * inv * g.y + b.y;
    o4.z = (v.z - mu) * inv * g.z + b.z;
    o4.w = (v.w - mu) * inv * g.w + b.w;
    ((float4*)(g_h + (size_t)warp * EMBED))[lane] = o4;
    ((float4*)(g_agg + (size_t)warp * EMBED))[lane] = o4;   // agg starts at h
}

// ---------------------------------------------------------------------------
// Kernel 2: fp16 mma.sync edge MLP. 128 edges/CTA, 8 warps, 2 CTAs/SM.
// (R9 version — at the HMMA issue floor; frozen)
// ---------------------------------------------------------------------------
#define TE 128
#define ETH 256
#define A_STRIDE 264   // halves; 528B rows -> 16B-rotating, ldmatrix conflict-free
#define B_STRIDE 136   // halves; 272B rows

#define SM_CI   0
#define SM_NI   512
#define SM_B1   1024
#define SM_B2   2048
#define SM_A    2560
#define SM_B    (SM_A + 128 * A_STRIDE * 2)   // 70144
#define EDGE_SMEM (SM_B + 128 * B_STRIDE * 2) // 104960  -> 2 CTAs/SM

__device__ __forceinline__ void cp_tile(uint32_t sdst,
                                        const __half* __restrict__ src,
                                        int src_stride_halves, int tid) {
    #pragma unroll
    for (int i = tid; i < 2048; i += ETH) {
        int r = i >> 4, c = i & 15;
        cpa16(sdst + r * (B_STRIDE * 2) + c * 16,
              src + r * src_stride_halves + c * 8);
    }
}

__global__ __launch_bounds__(ETH, 2)
void edge_kernel(const float* __restrict__ eemb,
                 const int* __restrict__ eidx,
                 const float* __restrict__ b1g,
                 const float* __restrict__ b2g) {
    extern __shared__ char smem[];
    uint32_t sbase = smem_u32(smem);
    int tid = threadIdx.x, wid = tid >> 5, lane = tid & 31;
    int e0 = blockIdx.x * TE;

    int*   s_ci = (int*)(smem + SM_CI);
    int*   s_ni = (int*)(smem + SM_NI);
    float* sb1  = (float*)(smem + SM_B1);
    float* sb2  = (float*)(smem + SM_B2);

    cp_tile(sbase + SM_B, g_w1h, 128, tid); CP_COMMIT();

    if (tid < 128) {
        s_ci[tid] = eidx[e0 + tid];
        s_ni[tid] = eidx[N_EDGES + e0 + tid];
    }
    sb1[tid] = b1g[tid];
    if (tid < 128) sb2[tid] = b2g[tid];
    __syncthreads();

    #pragma unroll
    for (int it = 0; it < 16; it++) {
        int v = tid + ETH * it;
        int m = v >> 5, c = v & 31;
        float4 ee = ((const float4*)(eemb + (size_t)(e0 + m) * EMBED))[c];
        float4 hc = ((const float4*)(g_h + (size_t)s_ci[m] * EMBED))[c];
        float4 hn = ((const float4*)(g_h + (size_t)s_ni[m] * EMBED))[c];
        float s0 = silu_f(ee.x + hc.x + hn.x);
        float s1 = silu_f(ee.y + hc.y + hn.y);
        float s2 = silu_f(ee.z + hc.z + hn.z);
        float s3 = silu_f(ee.w + hc.w + hn.w);
        __half2 p0 = __floats2half2_rn(s0, s1);
        __half2 p1 = __floats2half2_rn(s2, s3);
        int off = (m * A_STRIDE + 4 * c) * 2;
        *(__half2*)(smem + SM_A + off)     = p0;
        *(__half2*)(smem + SM_A + off + 4) = p1;
    }

    int rb = wid * 16;
    int ai = lane & 7, as_ = lane >> 3;
    int arow = rb + ai + (as_ & 1) * 8;
    int acolseg = (as_ >> 1) * 8;
    int bi = lane & 7, bs = (lane >> 3) & 1;
    int q = lane & 3;
    int r0 = rb + (lane >> 2), r1 = r0 + 8;

    // ================= GEMM1 (two n-halves) =================
    #pragma unroll 1
    for (int h = 0; h < 2; h++) {
        CP_WAIT(0);
        __syncthreads();

        float acc[16][4];
        #pragma unroll
        for (int i = 0; i < 16; i++)
            #pragma unroll
            for (int j = 0; j < 4; j++) acc[i][j] = 0.f;

        #pragma unroll
        for (int ks = 0; ks < 8; ks++) {
            uint32_t a4[4];
            uint32_t aoff = (uint32_t)(arow * A_STRIDE + ks * 16 + acolseg) * 2;
            ldm4(a4, sbase + SM_A + aoff);
            #pragma unroll
            for (int nt = 0; nt < 16; nt++) {
                uint32_t boff = (uint32_t)((nt * 8 + bi) * B_STRIDE + ks * 16 + bs * 8) * 2;
                uint32_t bw[2];
                ldm2(bw, sbase + SM_B + boff);
                mma_f16(acc[nt], a4, bw);
            }
        }
        __syncthreads();

        if (h == 0) { cp_tile(sbase + SM_B, g_w1h + 16384, 128, tid); CP_COMMIT(); }
        else        { cp_tile(sbase + SM_B, g_w2h,         256, tid); CP_COMMIT(); }

        int dbase = (h == 0) ? 128 : 0;
        #pragma unroll
        for (int nt = 0; nt < 16; nt++) {
            int c0 = nt * 8 + 2 * q;
            int gc = h * 128 + c0;
            float t0 = silu_f(acc[nt][0] + sb1[gc]);
            float t1 = silu_f(acc[nt][1] + sb1[gc + 1]);
            float t2 = silu_f(acc[nt][2] + sb1[gc]);
            float t3 = silu_f(acc[nt][3] + sb1[gc + 1]);
            int o0 = (r0 * A_STRIDE + dbase + c0) * 2;
            int o1 = (r1 * A_STRIDE + dbase + c0) * 2;
            *(__half2*)(smem + SM_A + o0) = __floats2half2_rn(t0, t1);
            *(__half2*)(smem + SM_A + o1) = __floats2half2_rn(t2, t3);
        }
    }

    // ================= GEMM2 (two k-phases) =============
    float acc2[16][4];
    #pragma unroll
    for (int i = 0; i < 16; i++)
        #pragma unroll
        for (int j = 0; j < 4; j++) acc2[i][j] = 0.f;

    #pragma unroll 1
    for (int ph = 0; ph < 2; ph++) {
        CP_WAIT(0);
        __syncthreads();

        int abase = (ph == 0) ? 128 : 0;
        #pragma unroll
        for (int ks = 0; ks < 8; ks++) {
            uint32_t a4[4];
            uint32_t aoff = (uint32_t)(arow * A_STRIDE + abase + ks * 16 + acolseg) * 2;
            ldm4(a4, sbase + SM_A + aoff);
            #pragma unroll
            for (int nt = 0; nt < 16; nt++) {
                uint32_t boff = (uint32_t)((nt * 8 + bi) * B_STRIDE + ks * 16 + bs * 8) * 2;
                uint32_t bw[2];
                ldm2(bw, sbase + SM_B + boff);
                mma_f16(acc2[nt], a4, bw);
            }
        }
        if (ph == 0) {
            __syncthreads();
            cp_tile(sbase + SM_B, g_w2h + 128, 256, tid); CP_COMMIT();
        }
    }

    // ---- epilogue ----
    {
        int ci0 = s_ci[r0], ci1 = s_ci[r1];
        int ni0 = s_ni[r0], ni1 = s_ni[r1];
        const float* hn0 = g_h + (size_t)ni0 * EMBED;
        const float* hn1 = g_h + (size_t)ni1 * EMBED;
        float* ag0 = g_agg + (size_t)ci0 * EMBED;
        float* ag1 = g_agg + (size_t)ci1 * EMBED;
        #pragma unroll
        for (int nt = 0; nt < 16; nt++) {
            int c0 = nt * 8 + 2 * q;
            float2 h0 = *(const float2*)(hn0 + c0);
            float2 h1 = *(const float2*)(hn1 + c0);
            atomicAdd(ag0 + c0,     (acc2[nt][0] + sb2[c0])     * h0.x);
            atomicAdd(ag0 + c0 + 1, (acc2[nt][1] + sb2[c0 + 1]) * h0.y);
            atomicAdd(ag1 + c0,     (acc2[nt][2] + sb2[c0])     * h1.x);
            atomicAdd(ag1 + c0 + 1, (acc2[nt][3] + sb2[c0 + 1]) * h1.y);
        }
    }
}

// ---------------------------------------------------------------------------
// Kernel 3: out = silu(g_agg) @ Wt + bt  (g_agg already holds h + agg)
// 64 rows/CTA, 256 threads, 3 CTAs/SM. ALL 8 warps do MMA:
// each warp owns 2 n-tiles (16 cols) x all 64 rows -> 32 acc regs.
// ---------------------------------------------------------------------------
#define ONR 64
#define OSM_BT  0
#define OSM_A   512
#define OSM_B   (OSM_A + ONR * B_STRIDE * 2)    // 17920
#define OUT_SMEM (OSM_B + 128 * B_STRIDE * 2)   // 52736

__device__ __forceinline__ void cp_tile_full(uint32_t sdst,
                                             const __half* __restrict__ src,
                                             int src_stride_halves, int tid) {
    #pragma unroll
    for (int i = tid; i < 2048; i += 256) {
        int r = i >> 4, c = i & 15;
        cpa16(sdst + r * (B_STRIDE * 2) + c * 16,
              src + r * src_stride_halves + c * 8);
    }
}

__global__ __launch_bounds__(256, 3)
void out_kernel(const float* __restrict__ btg, float* __restrict__ out) {
    extern __shared__ char smem[];
    uint32_t sbase = smem_u32(smem);
    int tid = threadIdx.x, wid = tid >> 5, lane = tid & 31;
    int n0 = blockIdx.x * ONR;

    float* sbt = (float*)(smem + OSM_BT);

    // prefetch Wt^T tile (overlaps gather)
    cp_tile_full(sbase + OSM_B, g_wth, 128, tid); CP_COMMIT();
    if (tid < 128) sbt[tid] = btg[tid];

    // ---- gather: A = fp16(silu(agg)) [64 rows x 128 cols] ----
    #pragma unroll
    for (int it = 0; it < 8; it++) {
        int v = tid + 256 * it;       // 0..2047
        int m = v >> 5, c = v & 31;
        int row = n0 + m;
        float s0 = 0.f, s1 = 0.f, s2 = 0.f, s3 = 0.f;
        if (row < N_NODES) {
            float4 av = ((const float4*)(g_agg + (size_t)row * EMBED))[c];
            s0 = silu_f(av.x);
            s1 = silu_f(av.y);
            s2 = silu_f(av.z);
            s3 = silu_f(av.w);
        }
        int off = (m * B_STRIDE + 4 * c) * 2;
        *(__half2*)(smem + OSM_A + off)     = __floats2half2_rn(s0, s1);
        *(__half2*)(smem + OSM_A + off + 4) = __floats2half2_rn(s2, s3);
    }

    CP_WAIT(0);
    __syncthreads();

    int ai = lane & 7, as_ = lane >> 3;
    int arowoff = ai + (as_ & 1) * 8;
    int acolseg = (as_ >> 1) * 8;
    int bi = lane & 7, bs = (lane >> 3) & 1;
    int q = lane & 3;
    int nb = wid * 2;   // this warp's two n-tiles

    float acc[4][2][4];
    #pragma unroll
    for (int i = 0; i < 4; i++)
        #pragma unroll
        for (int t = 0; t < 2; t++)
            #pragma unroll
            for (int j = 0; j < 4; j++) acc[i][t][j] = 0.f;

    #pragma unroll
    for (int ks = 0; ks < 8; ks++) {
        uint32_t bw0[2], bw1[2];
        ldm2(bw0, sbase + OSM_B + (uint32_t)(((nb + 0) * 8 + bi) * B_STRIDE + ks * 16 + bs * 8) * 2);
        ldm2(bw1, sbase + OSM_B + (uint32_t)(((nb + 1) * 8 + bi) * B_STRIDE + ks * 16 + bs * 8) * 2);
        #pragma unroll
        for (int mb = 0; mb < 4; mb++) {
            uint32_t a4[4];
            uint32_t aoff = (uint32_t)((mb * 16 + arowoff) * B_STRIDE + ks * 16 + acolseg) * 2;
            ldm4(a4, sbase + OSM_A + aoff);
            mma_f16(acc[mb][0], a4, bw0);
            mma_f16(acc[mb][1], a4, bw1);
        }
    }

    // ---- epilogue: out[row][c] = acc + bt[c] ----
    #pragma unroll
    for (int mb = 0; mb < 4; mb++) {
        int row0 = n0 + mb * 16 + (lane >> 2);
        int row1 = row0 + 8;
        #pragma unroll
        for (int t = 0; t < 2; t++) {
            int c0 = (nb + t) * 8 + 2 * q;
            float2 b2 = *(const float2*)(sbt + c0);
            if (row0 < N_NODES) {
                float2 o0 = make_float2(acc[mb][t][0] + b2.x, acc[mb][t][1] + b2.y);
                *(float2*)(out + (size_t)row0 * EMBED + c0) = o0;
            }
            if (row1 < N_NODES) {
                float2 o1 = make_float2(acc[mb][t][2] + b2.x, acc[mb][t][3] + b2.y);
                *(float2*)(out + (size_t)row1 * EMBED + c0) = o1;
            }
        }
    }
}

// ---------------------------------------------------------------------------
extern "C" void kernel_launch(void* const* d_in, const int* in_sizes, int n_in,
                              void* d_out, int out_size) {
    const float* node  = (const float*)d_in[0];
    const float* eemb  = (const float*)d_in[1];
    const int*   eidx  = (const int*)  d_in[2];
    const float* gamma = (const float*)d_in[3];
    const float* beta  = (const float*)d_in[4];
    const float* W1    = (const float*)d_in[5];
    const float* b1    = (const float*)d_in[6];
    const float* W2    = (const float*)d_in[7];
    const float* b2    = (const float*)d_in[8];
    const float* Wt    = (const float*)d_in[9];
    const float* bt    = (const float*)d_in[10];
    float* out = (float*)d_out;

    cudaFuncSetAttribute(edge_kernel, cudaFuncAttributeMaxDynamicSharedMemorySize,
                         EDGE_SMEM);
    cudaFuncSetAttribute(out_kernel, cudaFuncAttributeMaxDynamicSharedMemorySize,
                         OUT_SMEM);

    init_kernel<<<PREP_BLOCKS + (N_NODES + 7) / 8, 256>>>(node, gamma, beta, W1, W2, Wt);
    edge_kernel<<<N_EDGES / TE, ETH, EDGE_SMEM>>>(eemb, eidx, b1, b2);
    out_kernel<<<(N_NODES + ONR - 1) / ONR, 256, OUT_SMEM>>>(bt, out);
}

// round 12
// speedup vs baseline: 1.5301x; 1.0092x over previous
#include <cuda_runtime.h>
#include <cuda_fp16.h>
#include <cstdint>

#define N_NODES 50000
#define EMBED 128
#define HIDDEN 256
#define N_EDGES 640000
#define LN_EPS 1e-5f

// ---------------- warp MMA / cp.async helpers (sm_80-class) ----------------
__device__ __forceinline__ uint32_t smem_u32(const void* p) {
    uint32_t a;
    asm("{ .reg .u64 t; cvta.to.shared.u64 t, %1; cvt.u32.u64 %0, t; }"
        : "=r"(a) : "l"(p));
    return a;
}
__device__ __forceinline__ void mma_f16(float* d, const uint32_t* a, const uint32_t* b) {
    asm volatile(
        "mma.sync.aligned.m16n8k16.row.col.f32.f16.f16.f32 "
        "{%0,%1,%2,%3}, {%4,%5,%6,%7}, {%8,%9}, {%0,%1,%2,%3};"
        : "+f"(d[0]), "+f"(d[1]), "+f"(d[2]), "+f"(d[3])
        : "r"(a[0]), "r"(a[1]), "r"(a[2]), "r"(a[3]), "r"(b[0]), "r"(b[1]));
}
__device__ __forceinline__ void ldm4(uint32_t* r, uint32_t addr) {
    asm volatile("ldmatrix.sync.aligned.m8n8.x4.shared.b16 {%0,%1,%2,%3}, [%4];"
                 : "=r"(r[0]), "=r"(r[1]), "=r"(r[2]), "=r"(r[3]) : "r"(addr));
}
__device__ __forceinline__ void ldm2(uint32_t* r, uint32_t addr) {
    asm volatile("ldmatrix.sync.aligned.m8n8.x2.shared.b16 {%0,%1}, [%2];"
                 : "=r"(r[0]), "=r"(r[1]) : "r"(addr));
}
__device__ __forceinline__ void cpa16(uint32_t dst, const void* src) {
    asm volatile("cp.async.cg.shared.global [%0], [%1], 16;" :: "r"(dst), "l"(src));
}
#define CP_COMMIT() asm volatile("cp.async.commit_group;" ::: "memory")
#define CP_WAIT(n)  asm volatile("cp.async.wait_group %0;" :: "n"(n) : "memory")

__device__ __forceinline__ float silu_f(float x) {
    return __fdividef(x, 1.0f + __expf(-x));
}

// ---------------- device scratch ----------------
__device__ float g_h[N_NODES * EMBED];     // layernormed node embeddings
__device__ float g_agg[N_NODES * EMBED];   // init to h; edge atomics add msg -> h+agg
__device__ __align__(16) __half g_w1h[32768];   // W1^T [n=256][k=128]
__device__ __align__(16) __half g_w2h[32768];   // W2^T [n=128][kk=256]
__device__ __align__(16) __half g_wth[16384];   // Wt^T [n=128][k=128]

// ---------------------------------------------------------------------------
// Kernel 1 (fused): blocks 0..127 = weight prep; rest = LayerNorm (warp/row).
// ln writes h into BOTH g_h and g_agg (so edge atomics accumulate onto h).
// ---------------------------------------------------------------------------
#define PREP_BLOCKS 128

__global__ void init_kernel(const float* __restrict__ x,
                            const float* __restrict__ gamma,
                            const float* __restrict__ beta,
                            const float* __restrict__ W1,
                            const float* __restrict__ W2,
                            const float* __restrict__ Wt) {
    if (blockIdx.x < PREP_BLOCKS) {
        int idx = blockIdx.x * blockDim.x + threadIdx.x;   // 0..32767
        {   int k = idx >> 8, n = idx & 255;
            g_w1h[n * 128 + k] = __float2half_rn(W1[idx]); }
        {   int kk = idx >> 7, n = idx & 127;
            g_w2h[n * 256 + kk] = __float2half_rn(W2[idx]); }
        if (idx < 16384) {
            int k = idx >> 7, n = idx & 127;
            g_wth[n * 128 + k] = __float2half_rn(Wt[idx]);
        }
        return;
    }

    int warp = ((blockIdx.x - PREP_BLOCKS) * blockDim.x + threadIdx.x) >> 5;
    int lane = threadIdx.x & 31;
    if (warp >= N_NODES) return;

    const float4* row = (const float4*)(x + (size_t)warp * EMBED);
    float4 v = row[lane];
    float s  = v.x + v.y + v.z + v.w;
    float ss = v.x * v.x + v.y * v.y + v.z * v.z + v.w * v.w;
    #pragma unroll
    for (int o = 16; o; o >>= 1) {
        s  += __shfl_xor_sync(0xFFFFFFFFu, s,  o);
        ss += __shfl_xor_sync(0xFFFFFFFFu, ss, o);
    }
    const float inv_d = 1.0f / (float)EMBED;
    float mu  = s * inv_d;
    float var = ss * inv_d - mu * mu;
    float inv = rsqrtf(var + LN_EPS);

    float4 g = ((const float4*)gamma)[lane];
    float4 b = ((const float4*)beta)[lane];
    float4 o4;
    o4.x = (v.x - mu) * inv * g.x + b.x;
    o4.y = (v.y - mu) * inv * g.y + b.y;
    o4.z = (v.z - mu) * inv * g.z + b.z;
    o4.w = (v.w - mu) * inv * g.w + b.w;
    ((float4*)(g_h + (size_t)warp * EMBED))[lane] = o4;
    ((float4*)(g_agg + (size_t)warp * EMBED))[lane] = o4;   // agg starts at h
}

// ---------------------------------------------------------------------------
// Kernel 2: fp16 mma.sync edge MLP. 128 edges/CTA, 8 warps, 2 CTAs/SM.
// (R9 version — at the HMMA issue floor; FROZEN)
// ---------------------------------------------------------------------------
#define TE 128
#define ETH 256
#define A_STRIDE 264   // halves; 528B rows -> 16B-rotating, ldmatrix conflict-free
#define B_STRIDE 136   // halves; 272B rows

#define SM_CI   0
#define SM_NI   512
#define SM_B1   1024
#define SM_B2   2048
#define SM_A    2560
#define SM_B    (SM_A + 128 * A_STRIDE * 2)   // 70144
#define EDGE_SMEM (SM_B + 128 * B_STRIDE * 2) // 104960  -> 2 CTAs/SM

__device__ __forceinline__ void cp_tile(uint32_t sdst,
                                        const __half* __restrict__ src,
                                        int src_stride_halves, int tid) {
    #pragma unroll
    for (int i = tid; i < 2048; i += ETH) {
        int r = i >> 4, c = i & 15;
        cpa16(sdst + r * (B_STRIDE * 2) + c * 16,
              src + r * src_stride_halves + c * 8);
    }
}

__global__ __launch_bounds__(ETH, 2)
void edge_kernel(const float* __restrict__ eemb,
                 const int* __restrict__ eidx,
                 const float* __restrict__ b1g,
                 const float* __restrict__ b2g) {
    extern __shared__ char smem[];
    uint32_t sbase = smem_u32(smem);
    int tid = threadIdx.x, wid = tid >> 5, lane = tid & 31;
    int e0 = blockIdx.x * TE;

    int*   s_ci = (int*)(smem + SM_CI);
    int*   s_ni = (int*)(smem + SM_NI);
    float* sb1  = (float*)(smem + SM_B1);
    float* sb2  = (float*)(smem + SM_B2);

    cp_tile(sbase + SM_B, g_w1h, 128, tid); CP_COMMIT();

    if (tid < 128) {
        s_ci[tid] = eidx[e0 + tid];
        s_ni[tid] = eidx[N_EDGES + e0 + tid];
    }
    sb1[tid] = b1g[tid];
    if (tid < 128) sb2[tid] = b2g[tid];
    __syncthreads();

    #pragma unroll
    for (int it = 0; it < 16; it++) {
        int v = tid + ETH * it;
        int m = v >> 5, c = v & 31;
        float4 ee = ((const float4*)(eemb + (size_t)(e0 + m) * EMBED))[c];
        float4 hc = ((const float4*)(g_h + (size_t)s_ci[m] * EMBED))[c];
        float4 hn = ((const float4*)(g_h + (size_t)s_ni[m] * EMBED))[c];
        float s0 = silu_f(ee.x + hc.x + hn.x);
        float s1 = silu_f(ee.y + hc.y + hn.y);
        float s2 = silu_f(ee.z + hc.z + hn.z);
        float s3 = silu_f(ee.w + hc.w + hn.w);
        __half2 p0 = __floats2half2_rn(s0, s1);
        __half2 p1 = __floats2half2_rn(s2, s3);
        int off = (m * A_STRIDE + 4 * c) * 2;
        *(__half2*)(smem + SM_A + off)     = p0;
        *(__half2*)(smem + SM_A + off + 4) = p1;
    }

    int rb = wid * 16;
    int ai = lane & 7, as_ = lane >> 3;
    int arow = rb + ai + (as_ & 1) * 8;
    int acolseg = (as_ >> 1) * 8;
    int bi = lane & 7, bs = (lane >> 3) & 1;
    int q = lane & 3;
    int r0 = rb + (lane >> 2), r1 = r0 + 8;

    // ================= GEMM1 (two n-halves) =================
    #pragma unroll 1
    for (int h = 0; h < 2; h++) {
        CP_WAIT(0);
        __syncthreads();

        float acc[16][4];
        #pragma unroll
        for (int i = 0; i < 16; i++)
            #pragma unroll
            for (int j = 0; j < 4; j++) acc[i][j] = 0.f;

        #pragma unroll
        for (int ks = 0; ks < 8; ks++) {
            uint32_t a4[4];
            uint32_t aoff = (uint32_t)(arow * A_STRIDE + ks * 16 + acolseg) * 2;
            ldm4(a4, sbase + SM_A + aoff);
            #pragma unroll
            for (int nt = 0; nt < 16; nt++) {
                uint32_t boff = (uint32_t)((nt * 8 + bi) * B_STRIDE + ks * 16 + bs * 8) * 2;
                uint32_t bw[2];
                ldm2(bw, sbase + SM_B + boff);
                mma_f16(acc[nt], a4, bw);
            }
        }
        __syncthreads();

        if (h == 0) { cp_tile(sbase + SM_B, g_w1h + 16384, 128, tid); CP_COMMIT(); }
        else        { cp_tile(sbase + SM_B, g_w2h,         256, tid); CP_COMMIT(); }

        int dbase = (h == 0) ? 128 : 0;
        #pragma unroll
        for (int nt = 0; nt < 16; nt++) {
            int c0 = nt * 8 + 2 * q;
            int gc = h * 128 + c0;
            float t0 = silu_f(acc[nt][0] + sb1[gc]);
            float t1 = silu_f(acc[nt][1] + sb1[gc + 1]);
            float t2 = silu_f(acc[nt][2] + sb1[gc]);
            float t3 = silu_f(acc[nt][3] + sb1[gc + 1]);
            int o0 = (r0 * A_STRIDE + dbase + c0) * 2;
            int o1 = (r1 * A_STRIDE + dbase + c0) * 2;
            *(__half2*)(smem + SM_A + o0) = __floats2half2_rn(t0, t1);
            *(__half2*)(smem + SM_A + o1) = __floats2half2_rn(t2, t3);
        }
    }

    // ================= GEMM2 (two k-phases) =============
    float acc2[16][4];
    #pragma unroll
    for (int i = 0; i < 16; i++)
        #pragma unroll
        for (int j = 0; j < 4; j++) acc2[i][j] = 0.f;

    #pragma unroll 1
    for (int ph = 0; ph < 2; ph++) {
        CP_WAIT(0);
        __syncthreads();

        int abase = (ph == 0) ? 128 : 0;
        #pragma unroll
        for (int ks = 0; ks < 8; ks++) {
            uint32_t a4[4];
            uint32_t aoff = (uint32_t)(arow * A_STRIDE + abase + ks * 16 + acolseg) * 2;
            ldm4(a4, sbase + SM_A + aoff);
            #pragma unroll
            for (int nt = 0; nt < 16; nt++) {
                uint32_t boff = (uint32_t)((nt * 8 + bi) * B_STRIDE + ks * 16 + bs * 8) * 2;
                uint32_t bw[2];
                ldm2(bw, sbase + SM_B + boff);
                mma_f16(acc2[nt], a4, bw);
            }
        }
        if (ph == 0) {
            __syncthreads();
            cp_tile(sbase + SM_B, g_w2h + 128, 256, tid); CP_COMMIT();
        }
    }

    // ---- epilogue ----
    {
        int ci0 = s_ci[r0], ci1 = s_ci[r1];
        int ni0 = s_ni[r0], ni1 = s_ni[r1];
        const float* hn0 = g_h + (size_t)ni0 * EMBED;
        const float* hn1 = g_h + (size_t)ni1 * EMBED;
        float* ag0 = g_agg + (size_t)ci0 * EMBED;
        float* ag1 = g_agg + (size_t)ci1 * EMBED;
        #pragma unroll
        for (int nt = 0; nt < 16; nt++) {
            int c0 = nt * 8 + 2 * q;
            float2 h0 = *(const float2*)(hn0 + c0);
            float2 h1 = *(const float2*)(hn1 + c0);
            atomicAdd(ag0 + c0,     (acc2[nt][0] + sb2[c0])     * h0.x);
            atomicAdd(ag0 + c0 + 1, (acc2[nt][1] + sb2[c0 + 1]) * h0.y);
            atomicAdd(ag1 + c0,     (acc2[nt][2] + sb2[c0])     * h1.x);
            atomicAdd(ag1 + c0 + 1, (acc2[nt][3] + sb2[c0 + 1]) * h1.y);
        }
    }
}

// ---------------------------------------------------------------------------
// Kernel 3: out = silu(g_agg) @ Wt + bt  (g_agg already holds h + agg)
// R9 structure (64 rows/CTA, 256 thr, 3 CTAs/SM, warps 0-3 MMA) with the
// gather restructured into load-batches of 4 float4 (raises front MLP).
// ---------------------------------------------------------------------------
#define ONR 64
#define OSM_BT  0
#define OSM_A   512
#define OSM_B   (OSM_A + ONR * B_STRIDE * 2)    // 17920
#define OUT_SMEM (OSM_B + 128 * B_STRIDE * 2)   // 52736

__device__ __forceinline__ void cp_tile_full(uint32_t sdst,
                                             const __half* __restrict__ src,
                                             int src_stride_halves, int tid) {
    #pragma unroll
    for (int i = tid; i < 2048; i += 256) {
        int r = i >> 4, c = i & 15;
        cpa16(sdst + r * (B_STRIDE * 2) + c * 16,
              src + r * src_stride_halves + c * 8);
    }
}

__global__ __launch_bounds__(256, 3)
void out_kernel(const float* __restrict__ btg, float* __restrict__ out) {
    extern __shared__ char smem[];
    uint32_t sbase = smem_u32(smem);
    int tid = threadIdx.x, wid = tid >> 5, lane = tid & 31;
    int n0 = blockIdx.x * ONR;

    float* sbt = (float*)(smem + OSM_BT);

    // prefetch Wt^T tile (overlaps gather)
    cp_tile_full(sbase + OSM_B, g_wth, 128, tid); CP_COMMIT();
    if (tid < 128) sbt[tid] = btg[tid];

    // ---- gather: A = fp16(silu(agg)) [64 rows x 128 cols] ----
    // batched: 2 rounds of (4 loads in flight -> convert+store)
    #pragma unroll
    for (int bt = 0; bt < 2; bt++) {
        float4 av[4];
        int mm[4], cc[4];
        #pragma unroll
        for (int j = 0; j < 4; j++) {
            int v = tid + 256 * (bt * 4 + j);   // 0..2047
            mm[j] = v >> 5; cc[j] = v & 31;
            int row = n0 + mm[j];
            av[j] = make_float4(0.f, 0.f, 0.f, 0.f);
            if (row < N_NODES)
                av[j] = ((const float4*)(g_agg + (size_t)row * EMBED))[cc[j]];
        }
        #pragma unroll
        for (int j = 0; j < 4; j++) {
            float s0 = silu_f(av[j].x);
            float s1 = silu_f(av[j].y);
            float s2 = silu_f(av[j].z);
            float s3 = silu_f(av[j].w);
            int off = (mm[j] * B_STRIDE + 4 * cc[j]) * 2;
            *(__half2*)(smem + OSM_A + off)     = __floats2half2_rn(s0, s1);
            *(__half2*)(smem + OSM_A + off + 4) = __floats2half2_rn(s2, s3);
        }
    }

    CP_WAIT(0);
    __syncthreads();

    if (wid < 4) {
        int rb = wid * 16;
        int ai = lane & 7, as_ = lane >> 3;
        int arow = rb + ai + (as_ & 1) * 8;
        int acolseg = (as_ >> 1) * 8;
        int bi = lane & 7, bs = (lane >> 3) & 1;
        int q = lane & 3;
        int r0 = rb + (lane >> 2), r1 = r0 + 8;

        float acc[16][4];
        #pragma unroll
        for (int i = 0; i < 16; i++)
            #pragma unroll
            for (int j = 0; j < 4; j++) acc[i][j] = 0.f;

        #pragma unroll
        for (int ks = 0; ks < 8; ks++) {
            uint32_t a4[4];
            uint32_t aoff = (uint32_t)(arow * B_STRIDE + ks * 16 + acolseg) * 2;
            ldm4(a4, sbase + OSM_A + aoff);
            #pragma unroll
            for (int nt = 0; nt < 16; nt++) {
                uint32_t boff = (uint32_t)((nt * 8 + bi) * B_STRIDE + ks * 16 + bs * 8) * 2;
                uint32_t bw[2];
                ldm2(bw, sbase + OSM_B + boff);
                mma_f16(acc[nt], a4, bw);
            }
        }

        int row0 = n0 + r0, row1 = n0 + r1;
        #pragma unroll
        for (int nt = 0; nt < 16; nt++) {
            int c0 = nt * 8 + 2 * q;
            float2 b2 = *(const float2*)(sbt + c0);
            if (row0 < N_NODES) {
                float2 o0 = make_float2(acc[nt][0] + b2.x, acc[nt][1] + b2.y);
                *(float2*)(out + (size_t)row0 * EMBED + c0) = o0;
            }
            if (row1 < N_NODES) {
                float2 o1 = make_float2(acc[nt][2] + b2.x, acc[nt][3] + b2.y);
                *(float2*)(out + (size_t)row1 * EMBED + c0) = o1;
            }
        }
    }
}

// ---------------------------------------------------------------------------
extern "C" void kernel_launch(void* const* d_in, const int* in_sizes, int n_in,
                              void* d_out, int out_size) {
    const float* node  = (const float*)d_in[0];
    const float* eemb  = (const float*)d_in[1];
    const int*   eidx  = (const int*)  d_in[2];
    const float* gamma = (const float*)d_in[3];
    const float* beta  = (const float*)d_in[4];
    const float* W1    = (const float*)d_in[5];
    const float* b1    = (const float*)d_in[6];
    const float* W2    = (const float*)d_in[7];
    const float* b2    = (const float*)d_in[8];
    const float* Wt    = (const float*)d_in[9];
    const float* bt    = (const float*)d_in[10];
    float* out = (float*)d_out;

    cudaFuncSetAttribute(edge_kernel, cudaFuncAttributeMaxDynamicSharedMemorySize,
                         EDGE_SMEM);
    cudaFuncSetAttribute(out_kernel, cudaFuncAttributeMaxDynamicSharedMemorySize,
                         OUT_SMEM);

    init_kernel<<<PREP_BLOCKS + (N_NODES + 7) / 8, 256>>>(node, gamma, beta, W1, W2, Wt);
    edge_kernel<<<N_EDGES / TE, ETH, EDGE_SMEM>>>(eemb, eidx, b1, b2);
    out_kernel<<<(N_NODES + ONR - 1) / ONR, 256, OUT_SMEM>>>(bt, out);
}

// round 13
// speedup vs baseline: 1.5312x; 1.0007x over previous
#include <cuda_runtime.h>
#include <cuda_fp16.h>
#include <cstdint>

#define N_NODES 50000
#define EMBED 128
#define HIDDEN 256
#define N_EDGES 640000
#define LN_EPS 1e-5f

// ---------------- warp MMA / cp.async helpers (sm_80-class) ----------------
__device__ __forceinline__ uint32_t smem_u32(const void* p) {
    uint32_t a;
    asm("{ .reg .u64 t; cvta.to.shared.u64 t, %1; cvt.u32.u64 %0, t; }"
        : "=r"(a) : "l"(p));
    return a;
}
__device__ __forceinline__ void mma_f16(float* d, const uint32_t* a, const uint32_t* b) {
    asm volatile(
        "mma.sync.aligned.m16n8k16.row.col.f32.f16.f16.f32 "
        "{%0,%1,%2,%3}, {%4,%5,%6,%7}, {%8,%9}, {%0,%1,%2,%3};"
        : "+f"(d[0]), "+f"(d[1]), "+f"(d[2]), "+f"(d[3])
        : "r"(a[0]), "r"(a[1]), "r"(a[2]), "r"(a[3]), "r"(b[0]), "r"(b[1]));
}
__device__ __forceinline__ void ldm4(uint32_t* r, uint32_t addr) {
    asm volatile("ldmatrix.sync.aligned.m8n8.x4.shared.b16 {%0,%1,%2,%3}, [%4];"
                 : "=r"(r[0]), "=r"(r[1]), "=r"(r[2]), "=r"(r[3]) : "r"(addr));
}
__device__ __forceinline__ void ldm2(uint32_t* r, uint32_t addr) {
    asm volatile("ldmatrix.sync.aligned.m8n8.x2.shared.b16 {%0,%1}, [%2];"
                 : "=r"(r[0]), "=r"(r[1]) : "r"(addr));
}
__device__ __forceinline__ void cpa16(uint32_t dst, const void* src) {
    asm volatile("cp.async.cg.shared.global [%0], [%1], 16;" :: "r"(dst), "l"(src));
}
#define CP_COMMIT() asm volatile("cp.async.commit_group;" ::: "memory")
#define CP_WAIT(n)  asm volatile("cp.async.wait_group %0;" :: "n"(n) : "memory")

__device__ __forceinline__ float silu_f(float x) {
    return __fdividef(x, 1.0f + __expf(-x));
}

// ---------------- device scratch ----------------
__device__ float g_h[N_NODES * EMBED];     // layernormed node embeddings
__device__ float g_agg[N_NODES * EMBED];   // init to h; edge atomics add msg -> h+agg
__device__ __align__(16) __half g_w1h[32768];   // W1^T [n=256][k=128]
__device__ __align__(16) __half g_w2h[32768];   // W2^T [n=128][kk=256]
__device__ __align__(16) __half g_wth[16384];   // Wt^T [n=128][k=128]

// ---------------------------------------------------------------------------
// Kernel 1 (fused): blocks 0..127 = weight prep; rest = LayerNorm (warp/row).
// ln writes h into BOTH g_h and g_agg (so edge atomics accumulate onto h).
// ---------------------------------------------------------------------------
#define PREP_BLOCKS 128

__global__ void init_kernel(const float* __restrict__ x,
                            const float* __restrict__ gamma,
                            const float* __restrict__ beta,
                            const float* __restrict__ W1,
                            const float* __restrict__ W2,
                            const float* __restrict__ Wt) {
    if (blockIdx.x < PREP_BLOCKS) {
        int idx = blockIdx.x * blockDim.x + threadIdx.x;   // 0..32767
        {   int k = idx >> 8, n = idx & 255;
            g_w1h[n * 128 + k] = __float2half_rn(W1[idx]); }
        {   int kk = idx >> 7, n = idx & 127;
            g_w2h[n * 256 + kk] = __float2half_rn(W2[idx]); }
        if (idx < 16384) {
            int k = idx >> 7, n = idx & 127;
            g_wth[n * 128 + k] = __float2half_rn(Wt[idx]);
        }
        return;
    }

    int warp = ((blockIdx.x - PREP_BLOCKS) * blockDim.x + threadIdx.x) >> 5;
    int lane = threadIdx.x & 31;
    if (warp >= N_NODES) return;

    const float4* row = (const float4*)(x + (size_t)warp * EMBED);
    float4 v = row[lane];
    float s  = v.x + v.y + v.z + v.w;
    float ss = v.x * v.x + v.y * v.y + v.z * v.z + v.w * v.w;
    #pragma unroll
    for (int o = 16; o; o >>= 1) {
        s  += __shfl_xor_sync(0xFFFFFFFFu, s,  o);
        ss += __shfl_xor_sync(0xFFFFFFFFu, ss, o);
    }
    const float inv_d = 1.0f / (float)EMBED;
    float mu  = s * inv_d;
    float var = ss * inv_d - mu * mu;
    float inv = rsqrtf(var + LN_EPS);

    float4 g = ((const float4*)gamma)[lane];
    float4 b = ((const float4*)beta)[lane];
    float4 o4;
    o4.x = (v.x - mu) * inv * g.x + b.x;
    o4.y = (v.y - mu) * inv * g.y + b.y;
    o4.z = (v.z - mu) * inv * g.z + b.z;
    o4.w = (v.w - mu) * inv * g.w + b.w;
    ((float4*)(g_h + (size_t)warp * EMBED))[lane] = o4;
    ((float4*)(g_agg + (size_t)warp * EMBED))[lane] = o4;   // agg starts at h
}

// ---------------------------------------------------------------------------
// Kernel 2: fp16 mma.sync edge MLP. 128 edges/CTA, 8 warps, 2 CTAs/SM.
// (R9 version — at the HMMA issue floor; FROZEN)
// ---------------------------------------------------------------------------
#define TE 128
#define ETH 256
#define A_STRIDE 264   // halves; 528B rows -> 16B-rotating, ldmatrix conflict-free
#define B_STRIDE 136   // halves; 272B rows

#define SM_CI   0
#define SM_NI   512
#define SM_B1   1024
#define SM_B2   2048
#define SM_A    2560
#define SM_B    (SM_A + 128 * A_STRIDE * 2)   // 70144
#define EDGE_SMEM (SM_B + 128 * B_STRIDE * 2) // 104960  -> 2 CTAs/SM

__device__ __forceinline__ void cp_tile(uint32_t sdst,
                                        const __half* __restrict__ src,
                                        int src_stride_halves, int tid) {
    #pragma unroll
    for (int i = tid; i < 2048; i += ETH) {
        int r = i >> 4, c = i & 15;
        cpa16(sdst + r * (B_STRIDE * 2) + c * 16,
              src + r * src_stride_halves + c * 8);
    }
}

__global__ __launch_bounds__(ETH, 2)
void edge_kernel(const float* __restrict__ eemb,
                 const int* __restrict__ eidx,
                 const float* __restrict__ b1g,
                 const float* __restrict__ b2g) {
    extern __shared__ char smem[];
    uint32_t sbase = smem_u32(smem);
    int tid = threadIdx.x, wid = tid >> 5, lane = tid & 31;
    int e0 = blockIdx.x * TE;

    int*   s_ci = (int*)(smem + SM_CI);
    int*   s_ni = (int*)(smem + SM_NI);
    float* sb1  = (float*)(smem + SM_B1);
    float* sb2  = (float*)(smem + SM_B2);

    cp_tile(sbase + SM_B, g_w1h, 128, tid); CP_COMMIT();

    if (tid < 128) {
        s_ci[tid] = eidx[e0 + tid];
        s_ni[tid] = eidx[N_EDGES + e0 + tid];
    }
    sb1[tid] = b1g[tid];
    if (tid < 128) sb2[tid] = b2g[tid];
    __syncthreads();

    #pragma unroll
    for (int it = 0; it < 16; it++) {
        int v = tid + ETH * it;
        int m = v >> 5, c = v & 31;
        float4 ee = ((const float4*)(eemb + (size_t)(e0 + m) * EMBED))[c];
        float4 hc = ((const float4*)(g_h + (size_t)s_ci[m] * EMBED))[c];
        float4 hn = ((const float4*)(g_h + (size_t)s_ni[m] * EMBED))[c];
        float s0 = silu_f(ee.x + hc.x + hn.x);
        float s1 = silu_f(ee.y + hc.y + hn.y);
        float s2 = silu_f(ee.z + hc.z + hn.z);
        float s3 = silu_f(ee.w + hc.w + hn.w);
        __half2 p0 = __floats2half2_rn(s0, s1);
        __half2 p1 = __floats2half2_rn(s2, s3);
        int off = (m * A_STRIDE + 4 * c) * 2;
        *(__half2*)(smem + SM_A + off)     = p0;
        *(__half2*)(smem + SM_A + off + 4) = p1;
    }

    int rb = wid * 16;
    int ai = lane & 7, as_ = lane >> 3;
    int arow = rb + ai + (as_ & 1) * 8;
    int acolseg = (as_ >> 1) * 8;
    int bi = lane & 7, bs = (lane >> 3) & 1;
    int q = lane & 3;
    int r0 = rb + (lane >> 2), r1 = r0 + 8;

    // ================= GEMM1 (two n-halves) =================
    #pragma unroll 1
    for (int h = 0; h < 2; h++) {
        CP_WAIT(0);
        __syncthreads();

        float acc[16][4];
        #pragma unroll
        for (int i = 0; i < 16; i++)
            #pragma unroll
            for (int j = 0; j < 4; j++) acc[i][j] = 0.f;

        #pragma unroll
        for (int ks = 0; ks < 8; ks++) {
            uint32_t a4[4];
            uint32_t aoff = (uint32_t)(arow * A_STRIDE + ks * 16 + acolseg) * 2;
            ldm4(a4, sbase + SM_A + aoff);
            #pragma unroll
            for (int nt = 0; nt < 16; nt++) {
                uint32_t boff = (uint32_t)((nt * 8 + bi) * B_STRIDE + ks * 16 + bs * 8) * 2;
                uint32_t bw[2];
                ldm2(bw, sbase + SM_B + boff);
                mma_f16(acc[nt], a4, bw);
            }
        }
        __syncthreads();

        if (h == 0) { cp_tile(sbase + SM_B, g_w1h + 16384, 128, tid); CP_COMMIT(); }
        else        { cp_tile(sbase + SM_B, g_w2h,         256, tid); CP_COMMIT(); }

        int dbase = (h == 0) ? 128 : 0;
        #pragma unroll
        for (int nt = 0; nt < 16; nt++) {
            int c0 = nt * 8 + 2 * q;
            int gc = h * 128 + c0;
            float t0 = silu_f(acc[nt][0] + sb1[gc]);
            float t1 = silu_f(acc[nt][1] + sb1[gc + 1]);
            float t2 = silu_f(acc[nt][2] + sb1[gc]);
            float t3 = silu_f(acc[nt][3] + sb1[gc + 1]);
            int o0 = (r0 * A_STRIDE + dbase + c0) * 2;
            int o1 = (r1 * A_STRIDE + dbase + c0) * 2;
            *(__half2*)(smem + SM_A + o0) = __floats2half2_rn(t0, t1);
            *(__half2*)(smem + SM_A + o1) = __floats2half2_rn(t2, t3);
        }
    }

    // ================= GEMM2 (two k-phases) =============
    float acc2[16][4];
    #pragma unroll
    for (int i = 0; i < 16; i++)
        #pragma unroll
        for (int j = 0; j < 4; j++) acc2[i][j] = 0.f;

    #pragma unroll 1
    for (int ph = 0; ph < 2; ph++) {
        CP_WAIT(0);
        __syncthreads();

        int abase = (ph == 0) ? 128 : 0;
        #pragma unroll
        for (int ks = 0; ks < 8; ks++) {
            uint32_t a4[4];
            uint32_t aoff = (uint32_t)(arow * A_STRIDE + abase + ks * 16 + acolseg) * 2;
            ldm4(a4, sbase + SM_A + aoff);
            #pragma unroll
            for (int nt = 0; nt < 16; nt++) {
                uint32_t boff = (uint32_t)((nt * 8 + bi) * B_STRIDE + ks * 16 + bs * 8) * 2;
                uint32_t bw[2];
                ldm2(bw, sbase + SM_B + boff);
                mma_f16(acc2[nt], a4, bw);
            }
        }
        if (ph == 0) {
            __syncthreads();
            cp_tile(sbase + SM_B, g_w2h + 128, 256, tid); CP_COMMIT();
        }
    }

    // ---- epilogue ----
    {
        int ci0 = s_ci[r0], ci1 = s_ci[r1];
        int ni0 = s_ni[r0], ni1 = s_ni[r1];
        const float* hn0 = g_h + (size_t)ni0 * EMBED;
        const float* hn1 = g_h + (size_t)ni1 * EMBED;
        float* ag0 = g_agg + (size_t)ci0 * EMBED;
        float* ag1 = g_agg + (size_t)ci1 * EMBED;
        #pragma unroll
        for (int nt = 0; nt < 16; nt++) {
            int c0 = nt * 8 + 2 * q;
            float2 h0 = *(const float2*)(hn0 + c0);
            float2 h1 = *(const float2*)(hn1 + c0);
            atomicAdd(ag0 + c0,     (acc2[nt][0] + sb2[c0])     * h0.x);
            atomicAdd(ag0 + c0 + 1, (acc2[nt][1] + sb2[c0 + 1]) * h0.y);
            atomicAdd(ag1 + c0,     (acc2[nt][2] + sb2[c0])     * h1.x);
            atomicAdd(ag1 + c0 + 1, (acc2[nt][3] + sb2[c0 + 1]) * h1.y);
        }
    }
}

// ---------------------------------------------------------------------------
// Kernel 3: out = silu(g_agg) @ Wt + bt  (g_agg already holds h + agg)
// 64 rows/CTA, 256 threads, 4 CTAs/SM (smem 52.7KB, <=64 regs).
// ALL 8 warps do MMA (2 n-tiles each, 32 acc regs); batched gather.
// ---------------------------------------------------------------------------
#define ONR 64
#define OSM_BT  0
#define OSM_A   512
#define OSM_B   (OSM_A + ONR * B_STRIDE * 2)    // 17920
#define OUT_SMEM (OSM_B + 128 * B_STRIDE * 2)   // 52736

__device__ __forceinline__ void cp_tile_full(uint32_t sdst,
                                             const __half* __restrict__ src,
                                             int src_stride_halves, int tid) {
    #pragma unroll
    for (int i = tid; i < 2048; i += 256) {
        int r = i >> 4, c = i & 15;
        cpa16(sdst + r * (B_STRIDE * 2) + c * 16,
              src + r * src_stride_halves + c * 8);
    }
}

__global__ __launch_bounds__(256, 4)
void out_kernel(const float* __restrict__ btg, float* __restrict__ out) {
    extern __shared__ char smem[];
    uint32_t sbase = smem_u32(smem);
    int tid = threadIdx.x, wid = tid >> 5, lane = tid & 31;
    int n0 = blockIdx.x * ONR;

    float* sbt = (float*)(smem + OSM_BT);

    // prefetch Wt^T tile (overlaps gather)
    cp_tile_full(sbase + OSM_B, g_wth, 128, tid); CP_COMMIT();
    if (tid < 128) sbt[tid] = btg[tid];

    // ---- gather: A = fp16(silu(agg)) [64 rows x 128 cols] ----
    // batched: 2 rounds of (4 loads in flight -> convert+store)
    #pragma unroll
    for (int bt = 0; bt < 2; bt++) {
        float4 av[4];
        int mm[4], cc[4];
        #pragma unroll
        for (int j = 0; j < 4; j++) {
            int v = tid + 256 * (bt * 4 + j);   // 0..2047
            mm[j] = v >> 5; cc[j] = v & 31;
            int row = n0 + mm[j];
            av[j] = make_float4(0.f, 0.f, 0.f, 0.f);
            if (row < N_NODES)
                av[j] = ((const float4*)(g_agg + (size_t)row * EMBED))[cc[j]];
        }
        #pragma unroll
        for (int j = 0; j < 4; j++) {
            float s0 = silu_f(av[j].x);
            float s1 = silu_f(av[j].y);
            float s2 = silu_f(av[j].z);
            float s3 = silu_f(av[j].w);
            int off = (mm[j] * B_STRIDE + 4 * cc[j]) * 2;
            *(__half2*)(smem + OSM_A + off)     = __floats2half2_rn(s0, s1);
            *(__half2*)(smem + OSM_A + off + 4) = __floats2half2_rn(s2, s3);
        }
    }

    CP_WAIT(0);
    __syncthreads();

    int ai = lane & 7, as_ = lane >> 3;
    int arowoff = ai + (as_ & 1) * 8;
    int acolseg = (as_ >> 1) * 8;
    int bi = lane & 7, bs = (lane >> 3) & 1;
    int q = lane & 3;
    int nb = wid * 2;   // this warp's two n-tiles

    float acc[4][2][4];
    #pragma unroll
    for (int i = 0; i < 4; i++)
        #pragma unroll
        for (int t = 0; t < 2; t++)
            #pragma unroll
            for (int j = 0; j < 4; j++) acc[i][t][j] = 0.f;

    #pragma unroll
    for (int ks = 0; ks < 8; ks++) {
        uint32_t bw0[2], bw1[2];
        ldm2(bw0, sbase + OSM_B + (uint32_t)(((nb + 0) * 8 + bi) * B_STRIDE + ks * 16 + bs * 8) * 2);
        ldm2(bw1, sbase + OSM_B + (uint32_t)(((nb + 1) * 8 + bi) * B_STRIDE + ks * 16 + bs * 8) * 2);
        #pragma unroll
        for (int mb = 0; mb < 4; mb++) {
            uint32_t a4[4];
            uint32_t aoff = (uint32_t)((mb * 16 + arowoff) * B_STRIDE + ks * 16 + acolseg) * 2;
            ldm4(a4, sbase + OSM_A + aoff);
            mma_f16(acc[mb][0], a4, bw0);
            mma_f16(acc[mb][1], a4, bw1);
        }
    }

    // ---- epilogue: out[row][c] = acc + bt[c] ----
    #pragma unroll
    for (int mb = 0; mb < 4; mb++) {
        int row0 = n0 + mb * 16 + (lane >> 2);
        int row1 = row0 + 8;
        #pragma unroll
        for (int t = 0; t < 2; t++) {
            int c0 = (nb + t) * 8 + 2 * q;
            float2 b2 = *(const float2*)(sbt + c0);
            if (row0 < N_NODES) {
                float2 o0 = make_float2(acc[mb][t][0] + b2.x, acc[mb][t][1] + b2.y);
                *(float2*)(out + (size_t)row0 * EMBED + c0) = o0;
            }
            if (row1 < N_NODES) {
                float2 o1 = make_float2(acc[mb][t][2] + b2.x, acc[mb][t][3] + b2.y);
                *(float2*)(out + (size_t)row1 * EMBED + c0) = o1;
            }
        }
    }
}

// ---------------------------------------------------------------------------
extern "C" void kernel_launch(void* const* d_in, const int* in_sizes, int n_in,
                              void* d_out, int out_size) {
    const float* node  = (const float*)d_in[0];
    const float* eemb  = (const float*)d_in[1];
    const int*   eidx  = (const int*)  d_in[2];
    const float* gamma = (const float*)d_in[3];
    const float* beta  = (const float*)d_in[4];
    const float* W1    = (const float*)d_in[5];
    const float* b1    = (const float*)d_in[6];
    const float* W2    = (const float*)d_in[7];
    const float* b2    = (const float*)d_in[8];
    const float* Wt    = (const float*)d_in[9];
    const float* bt    = (const float*)d_in[10];
    float* out = (float*)d_out;

    cudaFuncSetAttribute(edge_kernel, cudaFuncAttributeMaxDynamicSharedMemorySize,
                         EDGE_SMEM);
    cudaFuncSetAttribute(out_kernel, cudaFuncAttributeMaxDynamicSharedMemorySize,
                         OUT_SMEM);

    init_kernel<<<PREP_BLOCKS + (N_NODES + 7) / 8, 256>>>(node, gamma, beta, W1, W2, Wt);
    edge_kernel<<<N_EDGES / TE, ETH, EDGE_SMEM>>>(eemb, eidx, b1, b2);
    out_kernel<<<(N_NODES + ONR - 1) / ONR, 256, OUT_SMEM>>>(bt, out);
}

// round 14
// speedup vs baseline: 1.6035x; 1.0472x over previous
#include <cuda_runtime.h>
#include <cuda_fp16.h>
#include <cstdint>

#define N_NODES 50000
#define EMBED 128
#define HIDDEN 256
#define N_EDGES 640000
#define LN_EPS 1e-5f

// ---------------- warp MMA / cp.async helpers (sm_80-class) ----------------
__device__ __forceinline__ uint32_t smem_u32(const void* p) {
    uint32_t a;
    asm("{ .reg .u64 t; cvta.to.shared.u64 t, %1; cvt.u32.u64 %0, t; }"
        : "=r"(a) : "l"(p));
    return a;
}
__device__ __forceinline__ void mma_f16(float* d, const uint32_t* a, const uint32_t* b) {
    asm volatile(
        "mma.sync.aligned.m16n8k16.row.col.f32.f16.f16.f32 "
        "{%0,%1,%2,%3}, {%4,%5,%6,%7}, {%8,%9}, {%0,%1,%2,%3};"
        : "+f"(d[0]), "+f"(d[1]), "+f"(d[2]), "+f"(d[3])
        : "r"(a[0]), "r"(a[1]), "r"(a[2]), "r"(a[3]), "r"(b[0]), "r"(b[1]));
}
__device__ __forceinline__ void ldm4(uint32_t* r, uint32_t addr) {
    asm volatile("ldmatrix.sync.aligned.m8n8.x4.shared.b16 {%0,%1,%2,%3}, [%4];"
                 : "=r"(r[0]), "=r"(r[1]), "=r"(r[2]), "=r"(r[3]) : "r"(addr));
}
__device__ __forceinline__ void ldm2(uint32_t* r, uint32_t addr) {
    asm volatile("ldmatrix.sync.aligned.m8n8.x2.shared.b16 {%0,%1}, [%2];"
                 : "=r"(r[0]), "=r"(r[1]) : "r"(addr));
}
__device__ __forceinline__ void cpa16(uint32_t dst, const void* src) {
    asm volatile("cp.async.cg.shared.global [%0], [%1], 16;" :: "r"(dst), "l"(src));
}
#define CP_COMMIT() asm volatile("cp.async.commit_group;" ::: "memory")
#define CP_WAIT(n)  asm volatile("cp.async.wait_group %0;" :: "n"(n) : "memory")

__device__ __forceinline__ float silu_f(float x) {
    return __fdividef(x, 1.0f + __expf(-x));
}

// ---------------- device scratch ----------------
__device__ float g_h[N_NODES * EMBED];     // layernormed node embeddings
__device__ float g_agg[N_NODES * EMBED];   // init to h; edge atomics add msg -> h+agg
__device__ __align__(16) __half g_w1h[32768];   // W1^T [n=256][k=128]
__device__ __align__(16) __half g_w2h[32768];   // W2^T [n=128][kk=256]
__device__ __align__(16) __half g_wth[16384];   // Wt^T [n=128][k=128]

// ---------------------------------------------------------------------------
// Kernel 1 (fused): blocks 0..127 = weight prep; rest = LayerNorm (warp/row).
// ln writes h into BOTH g_h and g_agg (so edge atomics accumulate onto h).
// ---------------------------------------------------------------------------
#define PREP_BLOCKS 128

__global__ void init_kernel(const float* __restrict__ x,
                            const float* __restrict__ gamma,
                            const float* __restrict__ beta,
                            const float* __restrict__ W1,
                            const float* __restrict__ W2,
                            const float* __restrict__ Wt) {
    if (blockIdx.x < PREP_BLOCKS) {
        int idx = blockIdx.x * blockDim.x + threadIdx.x;   // 0..32767
        {   int k = idx >> 8, n = idx & 255;
            g_w1h[n * 128 + k] = __float2half_rn(W1[idx]); }
        {   int kk = idx >> 7, n = idx & 127;
            g_w2h[n * 256 + kk] = __float2half_rn(W2[idx]); }
        if (idx < 16384) {
            int k = idx >> 7, n = idx & 127;
            g_wth[n * 128 + k] = __float2half_rn(Wt[idx]);
        }
        return;
    }

    int warp = ((blockIdx.x - PREP_BLOCKS) * blockDim.x + threadIdx.x) >> 5;
    int lane = threadIdx.x & 31;
    if (warp >= N_NODES) return;

    const float4* row = (const float4*)(x + (size_t)warp * EMBED);
    float4 v = row[lane];
    float s  = v.x + v.y + v.z + v.w;
    float ss = v.x * v.x + v.y * v.y + v.z * v.z + v.w * v.w;
    #pragma unroll
    for (int o = 16; o; o >>= 1) {
        s  += __shfl_xor_sync(0xFFFFFFFFu, s,  o);
        ss += __shfl_xor_sync(0xFFFFFFFFu, ss, o);
    }
    const float inv_d = 1.0f / (float)EMBED;
    float mu  = s * inv_d;
    float var = ss * inv_d - mu * mu;
    float inv = rsqrtf(var + LN_EPS);

    float4 g = ((const float4*)gamma)[lane];
    float4 b = ((const float4*)beta)[lane];
    float4 o4;
    o4.x = (v.x - mu) * inv * g.x + b.x;
    o4.y = (v.y - mu) * inv * g.y + b.y;
    o4.z = (v.z - mu) * inv * g.z + b.z;
    o4.w = (v.w - mu) * inv * g.w + b.w;
    ((float4*)(g_h + (size_t)warp * EMBED))[lane] = o4;
    ((float4*)(g_agg + (size_t)warp * EMBED))[lane] = o4;   // agg starts at h
}

// ---------------------------------------------------------------------------
// Kernel 2: fp16 mma.sync edge MLP. 128 edges/CTA, 8 warps, 2 CTAs/SM.
// R9 structure; gather restructured into batched load rounds (higher MLP).
// ---------------------------------------------------------------------------
#define TE 128
#define ETH 256
#define A_STRIDE 264   // halves; 528B rows -> 16B-rotating, ldmatrix conflict-free
#define B_STRIDE 136   // halves; 272B rows

#define SM_CI   0
#define SM_NI   512
#define SM_B1   1024
#define SM_B2   2048
#define SM_A    2560
#define SM_B    (SM_A + 128 * A_STRIDE * 2)   // 70144
#define EDGE_SMEM (SM_B + 128 * B_STRIDE * 2) // 104960  -> 2 CTAs/SM

__device__ __forceinline__ void cp_tile(uint32_t sdst,
                                        const __half* __restrict__ src,
                                        int src_stride_halves, int tid) {
    #pragma unroll
    for (int i = tid; i < 2048; i += ETH) {
        int r = i >> 4, c = i & 15;
        cpa16(sdst + r * (B_STRIDE * 2) + c * 16,
              src + r * src_stride_halves + c * 8);
    }
}

__global__ __launch_bounds__(ETH, 2)
void edge_kernel(const float* __restrict__ eemb,
                 const int* __restrict__ eidx,
                 const float* __restrict__ b1g,
                 const float* __restrict__ b2g) {
    extern __shared__ char smem[];
    uint32_t sbase = smem_u32(smem);
    int tid = threadIdx.x, wid = tid >> 5, lane = tid & 31;
    int e0 = blockIdx.x * TE;

    int*   s_ci = (int*)(smem + SM_CI);
    int*   s_ni = (int*)(smem + SM_NI);
    float* sb1  = (float*)(smem + SM_B1);
    float* sb2  = (float*)(smem + SM_B2);

    cp_tile(sbase + SM_B, g_w1h, 128, tid); CP_COMMIT();

    if (tid < 128) {
        s_ci[tid] = eidx[e0 + tid];
        s_ni[tid] = eidx[N_EDGES + e0 + tid];
    }
    sb1[tid] = b1g[tid];
    if (tid < 128) sb2[tid] = b2g[tid];
    __syncthreads();

    // ---- gather: A1 = fp16(silu(e + h_c + h_n)), batched 4 rounds x 4 slots ----
    #pragma unroll
    for (int bt = 0; bt < 4; bt++) {
        float4 ee[4], hc[4], hn[4];
        int mm[4], cc[4];
        #pragma unroll
        for (int j = 0; j < 4; j++) {
            int v = tid + ETH * (bt * 4 + j);   // 0..4095
            mm[j] = v >> 5; cc[j] = v & 31;
            ee[j] = ((const float4*)(eemb + (size_t)(e0 + mm[j]) * EMBED))[cc[j]];
            hc[j] = ((const float4*)(g_h + (size_t)s_ci[mm[j]] * EMBED))[cc[j]];
            hn[j] = ((const float4*)(g_h + (size_t)s_ni[mm[j]] * EMBED))[cc[j]];
        }
        #pragma unroll
        for (int j = 0; j < 4; j++) {
            float s0 = silu_f(ee[j].x + hc[j].x + hn[j].x);
            float s1 = silu_f(ee[j].y + hc[j].y + hn[j].y);
            float s2 = silu_f(ee[j].z + hc[j].z + hn[j].z);
            float s3 = silu_f(ee[j].w + hc[j].w + hn[j].w);
            int off = (mm[j] * A_STRIDE + 4 * cc[j]) * 2;
            *(__half2*)(smem + SM_A + off)     = __floats2half2_rn(s0, s1);
            *(__half2*)(smem + SM_A + off + 4) = __floats2half2_rn(s2, s3);
        }
    }

    int rb = wid * 16;
    int ai = lane & 7, as_ = lane >> 3;
    int arow = rb + ai + (as_ & 1) * 8;
    int acolseg = (as_ >> 1) * 8;
    int bi = lane & 7, bs = (lane >> 3) & 1;
    int q = lane & 3;
    int r0 = rb + (lane >> 2), r1 = r0 + 8;

    // ================= GEMM1 (two n-halves) =================
    #pragma unroll 1
    for (int h = 0; h < 2; h++) {
        CP_WAIT(0);
        __syncthreads();

        float acc[16][4];
        #pragma unroll
        for (int i = 0; i < 16; i++)
            #pragma unroll
            for (int j = 0; j < 4; j++) acc[i][j] = 0.f;

        #pragma unroll
        for (int ks = 0; ks < 8; ks++) {
            uint32_t a4[4];
            uint32_t aoff = (uint32_t)(arow * A_STRIDE + ks * 16 + acolseg) * 2;
            ldm4(a4, sbase + SM_A + aoff);
            #pragma unroll
            for (int nt = 0; nt < 16; nt++) {
                uint32_t boff = (uint32_t)((nt * 8 + bi) * B_STRIDE + ks * 16 + bs * 8) * 2;
                uint32_t bw[2];
                ldm2(bw, sbase + SM_B + boff);
                mma_f16(acc[nt], a4, bw);
            }
        }
        __syncthreads();

        if (h == 0) { cp_tile(sbase + SM_B, g_w1h + 16384, 128, tid); CP_COMMIT(); }
        else        { cp_tile(sbase + SM_B, g_w2h,         256, tid); CP_COMMIT(); }

        int dbase = (h == 0) ? 128 : 0;
        #pragma unroll
        for (int nt = 0; nt < 16; nt++) {
            int c0 = nt * 8 + 2 * q;
            int gc = h * 128 + c0;
            float t0 = silu_f(acc[nt][0] + sb1[gc]);
            float t1 = silu_f(acc[nt][1] + sb1[gc + 1]);
            float t2 = silu_f(acc[nt][2] + sb1[gc]);
            float t3 = silu_f(acc[nt][3] + sb1[gc + 1]);
            int o0 = (r0 * A_STRIDE + dbase + c0) * 2;
            int o1 = (r1 * A_STRIDE + dbase + c0) * 2;
            *(__half2*)(smem + SM_A + o0) = __floats2half2_rn(t0, t1);
            *(__half2*)(smem + SM_A + o1) = __floats2half2_rn(t2, t3);
        }
    }

    // ================= GEMM2 (two k-phases) =============
    float acc2[16][4];
    #pragma unroll
    for (int i = 0; i < 16; i++)
        #pragma unroll
        for (int j = 0; j < 4; j++) acc2[i][j] = 0.f;

    #pragma unroll 1
    for (int ph = 0; ph < 2; ph++) {
        CP_WAIT(0);
        __syncthreads();

        int abase = (ph == 0) ? 128 : 0;
        #pragma unroll
        for (int ks = 0; ks < 8; ks++) {
            uint32_t a4[4];
            uint32_t aoff = (uint32_t)(arow * A_STRIDE + abase + ks * 16 + acolseg) * 2;
            ldm4(a4, sbase + SM_A + aoff);
            #pragma unroll
            for (int nt = 0; nt < 16; nt++) {
                uint32_t boff = (uint32_t)((nt * 8 + bi) * B_STRIDE + ks * 16 + bs * 8) * 2;
                uint32_t bw[2];
                ldm2(bw, sbase + SM_B + boff);
                mma_f16(acc2[nt], a4, bw);
            }
        }
        if (ph == 0) {
            __syncthreads();
            cp_tile(sbase + SM_B, g_w2h + 128, 256, tid); CP_COMMIT();
        }
    }

    // ---- epilogue ----
    {
        int ci0 = s_ci[r0], ci1 = s_ci[r1];
        int ni0 = s_ni[r0], ni1 = s_ni[r1];
        const float* hn0 = g_h + (size_t)ni0 * EMBED;
        const float* hn1 = g_h + (size_t)ni1 * EMBED;
        float* ag0 = g_agg + (size_t)ci0 * EMBED;
        float* ag1 = g_agg + (size_t)ci1 * EMBED;
        #pragma unroll
        for (int nt = 0; nt < 16; nt++) {
            int c0 = nt * 8 + 2 * q;
            float2 h0 = *(const float2*)(hn0 + c0);
            float2 h1 = *(const float2*)(hn1 + c0);
            atomicAdd(ag0 + c0,     (acc2[nt][0] + sb2[c0])     * h0.x);
            atomicAdd(ag0 + c0 + 1, (acc2[nt][1] + sb2[c0 + 1]) * h0.y);
            atomicAdd(ag1 + c0,     (acc2[nt][2] + sb2[c0])     * h1.x);
            atomicAdd(ag1 + c0 + 1, (acc2[nt][3] + sb2[c0 + 1]) * h1.y);
        }
    }
}

// ---------------------------------------------------------------------------
// Kernel 3: out = silu(g_agg) @ Wt + bt  (R13 version, 4 CTAs/SM)
// ---------------------------------------------------------------------------
#define ONR 64
#define OSM_BT  0
#define OSM_A   512
#define OSM_B   (OSM_A + ONR * B_STRIDE * 2)    // 17920
#define OUT_SMEM (OSM_B + 128 * B_STRIDE * 2)   // 52736

__device__ __forceinline__ void cp_tile_full(uint32_t sdst,
                                             const __half* __restrict__ src,
                                             int src_stride_halves, int tid) {
    #pragma unroll
    for (int i = tid; i < 2048; i += 256) {
        int r = i >> 4, c = i & 15;
        cpa16(sdst + r * (B_STRIDE * 2) + c * 16,
              src + r * src_stride_halves + c * 8);
    }
}

__global__ __launch_bounds__(256, 4)
void out_kernel(const float* __restrict__ btg, float* __restrict__ out) {
    extern __shared__ char smem[];
    uint32_t sbase = smem_u32(smem);
    int tid = threadIdx.x, wid = tid >> 5, lane = tid & 31;
    int n0 = blockIdx.x * ONR;

    float* sbt = (float*)(smem + OSM_BT);

    cp_tile_full(sbase + OSM_B, g_wth, 128, tid); CP_COMMIT();
    if (tid < 128) sbt[tid] = btg[tid];

    #pragma unroll
    for (int bt = 0; bt < 2; bt++) {
        float4 av[4];
        int mm[4], cc[4];
        #pragma unroll
        for (int j = 0; j < 4; j++) {
            int v = tid + 256 * (bt * 4 + j);   // 0..2047
            mm[j] = v >> 5; cc[j] = v & 31;
            int row = n0 + mm[j];
            av[j] = make_float4(0.f, 0.f, 0.f, 0.f);
            if (row < N_NODES)
                av[j] = ((const float4*)(g_agg + (size_t)row * EMBED))[cc[j]];
        }
        #pragma unroll
        for (int j = 0; j < 4; j++) {
            float s0 = silu_f(av[j].x);
            float s1 = silu_f(av[j].y);
            float s2 = silu_f(av[j].z);
            float s3 = silu_f(av[j].w);
            int off = (mm[j] * B_STRIDE + 4 * cc[j]) * 2;
            *(__half2*)(smem + OSM_A + off)     = __floats2half2_rn(s0, s1);
            *(__half2*)(smem + OSM_A + off + 4) = __floats2half2_rn(s2, s3);
        }
    }

    CP_WAIT(0);
    __syncthreads();

    int ai = lane & 7, as_ = lane >> 3;
    int arowoff = ai + (as_ & 1) * 8;
    int acolseg = (as_ >> 1) * 8;
    int bi = lane & 7, bs = (lane >> 3) & 1;
    int q = lane & 3;
    int nb = wid * 2;   // this warp's two n-tiles

    float acc[4][2][4];
    #pragma unroll
    for (int i = 0; i < 4; i++)
        #pragma unroll
        for (int t = 0; t < 2; t++)
            #pragma unroll
            for (int j = 0; j < 4; j++) acc[i][t][j] = 0.f;

    #pragma unroll
    for (int ks = 0; ks < 8; ks++) {
        uint32_t bw0[2], bw1[2];
        ldm2(bw0, sbase + OSM_B + (uint32_t)(((nb + 0) * 8 + bi) * B_STRIDE + ks * 16 + bs * 8) * 2);
        ldm2(bw1, sbase + OSM_B + (uint32_t)(((nb + 1) * 8 + bi) * B_STRIDE + ks * 16 + bs * 8) * 2);
        #pragma unroll
        for (int mb = 0; mb < 4; mb++) {
            uint32_t a4[4];
            uint32_t aoff = (uint32_t)((mb * 16 + arowoff) * B_STRIDE + ks * 16 + acolseg) * 2;
            ldm4(a4, sbase + OSM_A + aoff);
            mma_f16(acc[mb][0], a4, bw0);
            mma_f16(acc[mb][1], a4, bw1);
        }
    }

    #pragma unroll
    for (int mb = 0; mb < 4; mb++) {
        int row0 = n0 + mb * 16 + (lane >> 2);
        int row1 = row0 + 8;
        #pragma unroll
        for (int t = 0; t < 2; t++) {
            int c0 = (nb + t) * 8 + 2 * q;
            float2 b2 = *(const float2*)(sbt + c0);
            if (row0 < N_NODES) {
                float2 o0 = make_float2(acc[mb][t][0] + b2.x, acc[mb][t][1] + b2.y);
                *(float2*)(out + (size_t)row0 * EMBED + c0) = o0;
            }
            if (row1 < N_NODES) {
                float2 o1 = make_float2(acc[mb][t][2] + b2.x, acc[mb][t][3] + b2.y);
                *(float2*)(out + (size_t)row1 * EMBED + c0) = o1;
            }
        }
    }
}

// ---------------------------------------------------------------------------
extern "C" void kernel_launch(void* const* d_in, const int* in_sizes, int n_in,
                              void* d_out, int out_size) {
    const float* node  = (const float*)d_in[0];
    const float* eemb  = (const float*)d_in[1];
    const int*   eidx  = (const int*)  d_in[2];
    const float* gamma = (const float*)d_in[3];
    const float* beta  = (const float*)d_in[4];
    const float* W1    = (const float*)d_in[5];
    const float* b1    = (const float*)d_in[6];
    const float* W2    = (const float*)d_in[7];
    const float* b2    = (const float*)d_in[8];
    const float* Wt    = (const float*)d_in[9];
    const float* bt    = (const float*)d_in[10];
    float* out = (float*)d_out;

    cudaFuncSetAttribute(edge_kernel, cudaFuncAttributeMaxDynamicSharedMemorySize,
                         EDGE_SMEM);
    cudaFuncSetAttribute(out_kernel, cudaFuncAttributeMaxDynamicSharedMemorySize,
                         OUT_SMEM);

    init_kernel<<<PREP_BLOCKS + (N_NODES + 7) / 8, 256>>>(node, gamma, beta, W1, W2, Wt);
    edge_kernel<<<N_EDGES / TE, ETH, EDGE_SMEM>>>(eemb, eidx, b1, b2);
    out_kernel<<<(N_NODES + ONR - 1) / ONR, 256, OUT_SMEM>>>(bt, out);
}